// round 13
// baseline (speedup 1.0000x reference)
#include <cuda_runtime.h>
#include <cuda.h>
#include <cuda_bf16.h>
#include <math.h>
#include <stdint.h>

#define IN_F   4096
#define OUT_F  1024
#define BSZ    8192
#define COLS   9216
#define COLS4  2304
#define GROUPS 2048
#define ROUNDS 12

#define KCH    128            // int8 elems per chunk = 128 bytes
#define CHPS   32             // chunks per segment
#define NSEG   9
#define NCH    (NSEG * CHPS)  // 288
#define NSTG   4
#define A_BYTES (128 * 128)
#define B_BYTES (64 * 128)
#define ST_BYTES (A_BYTES + B_BYTES)
#define DSMEM (1024 + NSTG * ST_BYTES)

// ---------------- device scratch ----------------
__device__ __align__(128) float g_a[(size_t)IN_F * COLS];
__device__ __align__(128) float g_b[(size_t)IN_F * COLS];
__device__ __align__(128) float g_wmats[ROUNDS * GROUPS * 4];
__device__ unsigned g_mm[4];
__device__ unsigned g_amax[4];       // maxabs: x, nx, wn, wp
__device__ float    g_qp[4];         // sx, zx, sw, zw
__device__ float    g_cs[16];        // 4 tensors x {s1, is1, s2, is2}
__device__ float    g_segscale[12];
__device__ int      g_sums[COLS];    // Sx[0..8191], Sw at +BSZ

__device__ __align__(128) int8_t g_qx8 [(size_t)BSZ   * IN_F];
__device__ __align__(128) int8_t g_q1x [(size_t)BSZ   * IN_F];
__device__ __align__(128) int8_t g_q2x [(size_t)BSZ   * IN_F];
__device__ __align__(128) int8_t g_q1nx[(size_t)BSZ   * IN_F];
__device__ __align__(128) int8_t g_q2nx[(size_t)BSZ   * IN_F];
__device__ __align__(128) int8_t g_qw8 [(size_t)OUT_F * IN_F];
__device__ __align__(128) int8_t g_q1wn[(size_t)OUT_F * IN_F];
__device__ __align__(128) int8_t g_q2wn[(size_t)OUT_F * IN_F];
__device__ __align__(128) int8_t g_q1wp[(size_t)OUT_F * IN_F];
__device__ __align__(128) int8_t g_q2wp[(size_t)OUT_F * IN_F];

struct TmapPack { CUtensorMap a[5]; CUtensorMap b[5]; };

// ---------------- helpers ----------------
__device__ __forceinline__ unsigned enc_f(float f) {
    unsigned u = __float_as_uint(f);
    return (u & 0x80000000u) ? ~u : (u | 0x80000000u);
}
__device__ __forceinline__ float dec_f(unsigned k) {
    return __uint_as_float((k & 0x80000000u) ? (k ^ 0x80000000u) : ~k);
}
__device__ __forceinline__ uint32_t smem_u32(const void* p) {
    uint32_t a;
    asm("{ .reg .u64 t; cvta.to.shared.u64 t, %1; cvt.u32.u64 %0, t; }" : "=r"(a) : "l"(p));
    return a;
}

#define MBAR_INIT(addr, cnt) \
    asm volatile("mbarrier.init.shared.b64 [%0], %1;" :: "r"(addr), "r"(cnt) : "memory")
#define MBAR_EXPECT_TX(addr, bytes) \
    asm volatile("mbarrier.arrive.expect_tx.shared.b64 _, [%0], %1;" :: "r"(addr), "r"(bytes) : "memory")
#define MBAR_WAIT(addr, par) do {                                              \
    asm volatile(                                                              \
        "{\n\t.reg .pred P;\n\t"                                               \
        "WL_%=:\n\t"                                                           \
        "mbarrier.try_wait.parity.acquire.cta.shared::cta.b64 P, [%0], %1, 0x989680;\n\t" \
        "@P bra.uni WD_%=;\n\t"                                                \
        "bra.uni WL_%=;\n\t"                                                   \
        "WD_%=:\n\t}"                                                          \
        :: "r"(addr), "r"(par) : "memory");                                    \
} while (0)

#define TMA_2D(smem, map, cx, cy, mbar) \
    asm volatile("cp.async.bulk.tensor.2d.shared::cta.global.tile.mbarrier::complete_tx::bytes " \
                 "[%0], [%1, {%2, %3}], [%4];" \
                 :: "r"(smem), "l"(map), "r"(cx), "r"(cy), "r"(mbar) : "memory")

// ---------------- inv(m)^T via LU w/ partial pivoting ----------------
__global__ void make_wmats_kernel(const float* __restrict__ mats) {
    int idx = blockIdx.x * blockDim.x + threadIdx.x;
    if (idx >= ROUNDS * GROUPS) return;
    const float* m = mats + (size_t)idx * 4;
    float a = m[0], b = m[1], c = m[2], d = m[3];
    float i00, i01, i10, i11;
    if (fabsf(c) > fabsf(a)) {
        float l   = __fdiv_rn(a, c);
        float u22 = __fmaf_rn(-l, d, b);
        float x2c1 = __fdiv_rn(1.0f, u22);
        float x1c1 = __fdiv_rn(__fmul_rn(-d, x2c1), c);
        float x2c2 = __fdiv_rn(-l, u22);
        float x1c2 = __fdiv_rn(__fmaf_rn(-d, x2c2, 1.0f), c);
        i00 = x1c1; i01 = x1c2; i10 = x2c1; i11 = x2c2;
    } else {
        float l   = __fdiv_rn(c, a);
        float u22 = __fmaf_rn(-l, b, d);
        float x2c1 = __fdiv_rn(-l, u22);
        float x1c1 = __fdiv_rn(__fmaf_rn(-b, x2c1, 1.0f), a);
        float x2c2 = __fdiv_rn(1.0f, u22);
        float x1c2 = __fdiv_rn(__fmul_rn(-b, x2c2), a);
        i00 = x1c1; i01 = x1c2; i10 = x2c1; i11 = x2c2;
    }
    float* o = g_wmats + (size_t)idx * 4;
    o[0] = i00; o[1] = i10; o[2] = i01; o[3] = i11;
}

// ---------------- init ----------------
__global__ void reset_kernel() {
    int t = blockIdx.x * blockDim.x + threadIdx.x;
    if (t == 0) {
        g_mm[0] = 0xFFFFFFFFu; g_mm[1] = 0u;
        g_mm[2] = 0xFFFFFFFFu; g_mm[3] = 0u;
        g_amax[0] = 0; g_amax[1] = 0; g_amax[2] = 0; g_amax[3] = 0;
    }
    if (t < COLS) g_sums[t] = 0;
}

// ---------------- maxabs reductions ----------------
__global__ void maxabs_x_kernel(const float* __restrict__ x, const float* __restrict__ nx) {
    const size_t N4 = (size_t)BSZ * IN_F / 4;
    float mx = 0.f, mn = 0.f;
    for (size_t i = (size_t)blockIdx.x * blockDim.x + threadIdx.x; i < N4;
         i += (size_t)gridDim.x * blockDim.x) {
        float4 vx = ((const float4*)x)[i];
        float4 vn = ((const float4*)nx)[i];
        mx = fmaxf(mx, fmaxf(fmaxf(fabsf(vx.x), fabsf(vx.y)), fmaxf(fabsf(vx.z), fabsf(vx.w))));
        mn = fmaxf(mn, fmaxf(fmaxf(fabsf(vn.x), fabsf(vn.y)), fmaxf(fabsf(vn.z), fabsf(vn.w))));
    }
    __shared__ float red[256];
    red[threadIdx.x] = mx; __syncthreads();
    for (int s = 128; s > 0; s >>= 1) {
        if (threadIdx.x < s) red[threadIdx.x] = fmaxf(red[threadIdx.x], red[threadIdx.x + s]);
        __syncthreads();
    }
    if (threadIdx.x == 0) atomicMax(&g_amax[0], __float_as_uint(red[0]));
    __syncthreads();
    red[threadIdx.x] = mn; __syncthreads();
    for (int s = 128; s > 0; s >>= 1) {
        if (threadIdx.x < s) red[threadIdx.x] = fmaxf(red[threadIdx.x], red[threadIdx.x + s]);
        __syncthreads();
    }
    if (threadIdx.x == 0) atomicMax(&g_amax[1], __float_as_uint(red[0]));
}
__global__ void maxabs_w_kernel(const float* __restrict__ w, const float* __restrict__ wn) {
    const size_t N4 = (size_t)OUT_F * IN_F / 4;
    float m2 = 0.f, m3 = 0.f;
    for (size_t i = (size_t)blockIdx.x * blockDim.x + threadIdx.x; i < N4;
         i += (size_t)gridDim.x * blockDim.x) {
        float4 vw = ((const float4*)w)[i];
        float4 vn = ((const float4*)wn)[i];
        m2 = fmaxf(m2, fmaxf(fmaxf(fabsf(vn.x), fabsf(vn.y)), fmaxf(fabsf(vn.z), fabsf(vn.w))));
        float p0 = __fadd_rn(vw.x, vn.x), p1 = __fadd_rn(vw.y, vn.y);
        float p2 = __fadd_rn(vw.z, vn.z), p3 = __fadd_rn(vw.w, vn.w);
        m3 = fmaxf(m3, fmaxf(fmaxf(fabsf(p0), fabsf(p1)), fmaxf(fabsf(p2), fabsf(p3))));
    }
    __shared__ float red[256];
    red[threadIdx.x] = m2; __syncthreads();
    for (int s = 128; s > 0; s >>= 1) {
        if (threadIdx.x < s) red[threadIdx.x] = fmaxf(red[threadIdx.x], red[threadIdx.x + s]);
        __syncthreads();
    }
    if (threadIdx.x == 0) atomicMax(&g_amax[2], __float_as_uint(red[0]));
    __syncthreads();
    red[threadIdx.x] = m3; __syncthreads();
    for (int s = 128; s > 0; s >>= 1) {
        if (threadIdx.x < s) red[threadIdx.x] = fmaxf(red[threadIdx.x], red[threadIdx.x + s]);
        __syncthreads();
    }
    if (threadIdx.x == 0) atomicMax(&g_amax[3], __float_as_uint(red[0]));
}

__global__ void scalesA_kernel() {
    if (threadIdx.x == 0) {
        for (int t = 0; t < 4; t++) {
            float am = __uint_as_float(g_amax[t]);
            float s1 = __fdiv_rn(am, 127.0f);
            float is1 = __fdiv_rn(127.0f, am);
            float s2 = __fdiv_rn(s1, 254.0f);
            float is2 = __fdiv_rn(1.0f, s2);
            g_cs[t * 4 + 0] = s1; g_cs[t * 4 + 1] = is1;
            g_cs[t * 4 + 2] = s2; g_cs[t * 4 + 3] = is2;
        }
    }
}

// ---------------- residual int8 quant helper ----------------
__device__ __forceinline__ void q2lvl(float v, float s1, float is1, float is2,
                                      int8_t& o1, int8_t& o2) {
    float q1 = rintf(__fmul_rn(v, is1));
    q1 = fminf(fmaxf(q1, -127.0f), 127.0f);
    float r = __fmaf_rn(-q1, s1, v);
    float q2 = rintf(__fmul_rn(r, is2));
    q2 = fminf(fmaxf(q2, -127.0f), 127.0f);
    o1 = (int8_t)(int)q1;
    o2 = (int8_t)(int)q2;
}

// ---------------- fused transpose+add + residual int8 quant ----------------
__global__ void prepsplit_x_kernel(const float* __restrict__ x, const float* __restrict__ nx) {
    __shared__ float tile[32][33];
    int c0 = blockIdx.x * 32, k0 = blockIdx.y * 32;
    int tx = threadIdx.x, ty = threadIdx.y;
    float s1x = g_cs[0], is1x = g_cs[1], is2x = g_cs[3];
    float s1n = g_cs[4], is1n = g_cs[5], is2n = g_cs[7];
#pragma unroll
    for (int i = ty; i < 32; i += 8) {
        size_t idx = (size_t)(c0 + i) * IN_F + k0 + tx;
        float vx = x[idx], vn = nx[idx];
        tile[i][tx] = __fadd_rn(vx, vn);
        int8_t a, b;
        q2lvl(vx, s1x, is1x, is2x, a, b);  g_q1x[idx]  = a; g_q2x[idx]  = b;
        q2lvl(vn, s1n, is1n, is2n, a, b);  g_q1nx[idx] = a; g_q2nx[idx] = b;
    }
    __syncthreads();
#pragma unroll
    for (int i = ty; i < 32; i += 8)
        g_a[(size_t)(k0 + i) * COLS + c0 + tx] = tile[tx][i];
}
__global__ void prepsplit_w_kernel(const float* __restrict__ w, const float* __restrict__ wn) {
    __shared__ float tile[32][33];
    int c0 = blockIdx.x * 32, k0 = blockIdx.y * 32;
    int tx = threadIdx.x, ty = threadIdx.y;
    float s1n = g_cs[8],  is1n = g_cs[9],  is2n = g_cs[11];
    float s1p = g_cs[12], is1p = g_cs[13], is2p = g_cs[15];
#pragma unroll
    for (int i = ty; i < 32; i += 8) {
        size_t idx = (size_t)(c0 + i) * IN_F + k0 + tx;
        float vw = w[idx], vn = wn[idx];
        float vp = __fadd_rn(vw, vn);
        tile[i][tx] = vp;
        int8_t a, b;
        q2lvl(vn, s1n, is1n, is2n, a, b);  g_q1wn[idx] = a; g_q2wn[idx] = b;
        q2lvl(vp, s1p, is1p, is2p, a, b);  g_q1wp[idx] = a; g_q2wp[idx] = b;
    }
    __syncthreads();
#pragma unroll
    for (int i = ty; i < 32; i += 8)
        g_a[(size_t)(k0 + i) * COLS + BSZ + c0 + tx] = tile[tx][i];
}

// ---------------- TWO fused permutation + 2x2-mix rounds (NO FMA) ----------------
__global__ void round2_kernel(int dir, int r,
                              const int* __restrict__ perm0,
                              const int* __restrict__ perm1,
                              const float* __restrict__ matsx0,
                              const float* __restrict__ matsx1,
                              int do_mm) {
    const float* in  = dir ? g_b : g_a;
    float*       out = dir ? g_a : g_b;
    int g   = blockIdx.y;
    int col = blockIdx.x * 256 + threadIdx.x;
    int i0 = __ldg(&perm1[2 * g]);
    int i1 = __ldg(&perm1[2 * g + 1]);
    int g0 = i0 >> 1, p0 = i0 & 1;
    int g1 = i1 >> 1, p1 = i1 & 1;
    int ra0 = __ldg(&perm0[2 * g0]), rb0 = __ldg(&perm0[2 * g0 + 1]);
    int ra1 = __ldg(&perm0[2 * g1]), rb1 = __ldg(&perm0[2 * g1 + 1]);
    bool isx = (col < BSZ / 4);
    const float* m0base = isx ? matsx0 : (g_wmats + (size_t)r * GROUPS * 4);
    const float* m1base = isx ? matsx1 : (g_wmats + (size_t)(r + 1) * GROUPS * 4);
    float4 mA = __ldg((const float4*)(m0base + (size_t)g0 * 4));
    float4 mB = __ldg((const float4*)(m0base + (size_t)g1 * 4));
    float4 mC = __ldg((const float4*)(m1base + (size_t)g * 4));
    float c00 = p0 ? mA.z : mA.x, c01 = p0 ? mA.w : mA.y;
    float c10 = p1 ? mB.z : mB.x, c11 = p1 ? mB.w : mB.y;
    float4 a0 = ((const float4*)(in + (size_t)ra0 * COLS))[col];
    float4 b0 = ((const float4*)(in + (size_t)rb0 * COLS))[col];
    float4 a1 = ((const float4*)(in + (size_t)ra1 * COLS))[col];
    float4 b1 = ((const float4*)(in + (size_t)rb1 * COLS))[col];
    float4 v0, v1, o0, o1;
    v0.x = __fadd_rn(__fmul_rn(c00, a0.x), __fmul_rn(c01, b0.x));
    v0.y = __fadd_rn(__fmul_rn(c00, a0.y), __fmul_rn(c01, b0.y));
    v0.z = __fadd_rn(__fmul_rn(c00, a0.z), __fmul_rn(c01, b0.z));
    v0.w = __fadd_rn(__fmul_rn(c00, a0.w), __fmul_rn(c01, b0.w));
    v1.x = __fadd_rn(__fmul_rn(c10, a1.x), __fmul_rn(c11, b1.x));
    v1.y = __fadd_rn(__fmul_rn(c10, a1.y), __fmul_rn(c11, b1.y));
    v1.z = __fadd_rn(__fmul_rn(c10, a1.z), __fmul_rn(c11, b1.z));
    v1.w = __fadd_rn(__fmul_rn(c10, a1.w), __fmul_rn(c11, b1.w));
    o0.x = __fadd_rn(__fmul_rn(mC.x, v0.x), __fmul_rn(mC.y, v1.x));
    o0.y = __fadd_rn(__fmul_rn(mC.x, v0.y), __fmul_rn(mC.y, v1.y));
    o0.z = __fadd_rn(__fmul_rn(mC.x, v0.z), __fmul_rn(mC.y, v1.z));
    o0.w = __fadd_rn(__fmul_rn(mC.x, v0.w), __fmul_rn(mC.y, v1.w));
    o1.x = __fadd_rn(__fmul_rn(mC.z, v0.x), __fmul_rn(mC.w, v1.x));
    o1.y = __fadd_rn(__fmul_rn(mC.z, v0.y), __fmul_rn(mC.w, v1.y));
    o1.z = __fadd_rn(__fmul_rn(mC.z, v0.z), __fmul_rn(mC.w, v1.z));
    o1.w = __fadd_rn(__fmul_rn(mC.z, v0.w), __fmul_rn(mC.w, v1.w));
    ((float4*)(out + (size_t)(2 * g)     * COLS))[col] = o0;
    ((float4*)(out + (size_t)(2 * g + 1) * COLS))[col] = o1;

    if (do_mm) {
        float lo = fminf(fminf(fminf(o0.x, o0.y), fminf(o0.z, o0.w)),
                         fminf(fminf(o1.x, o1.y), fminf(o1.z, o1.w)));
        float hi = fmaxf(fmaxf(fmaxf(o0.x, o0.y), fmaxf(o0.z, o0.w)),
                         fmaxf(fmaxf(o1.x, o1.y), fmaxf(o1.z, o1.w)));
        __shared__ float red[256];
        red[threadIdx.x] = lo; __syncthreads();
        for (int s = 128; s > 0; s >>= 1) {
            if (threadIdx.x < s) red[threadIdx.x] = fminf(red[threadIdx.x], red[threadIdx.x + s]);
            __syncthreads();
        }
        if (threadIdx.x == 0) atomicMin(&g_mm[isx ? 0 : 2], enc_f(red[0]));
        __syncthreads();
        red[threadIdx.x] = hi; __syncthreads();
        for (int s = 128; s > 0; s >>= 1) {
            if (threadIdx.x < s) red[threadIdx.x] = fmaxf(red[threadIdx.x], red[threadIdx.x + s]);
            __syncthreads();
        }
        if (threadIdx.x == 0) atomicMax(&g_mm[isx ? 1 : 3], enc_f(red[0]));
    }
}

// ---------------- qparams + segment scales ----------------
__global__ void qparams_kernel() {
    if (threadIdx.x == 0) {
        float lx = dec_f(g_mm[0]), hx = dec_f(g_mm[1]);
        float sx = __fdiv_rn(__fsub_rn(hx, lx), 255.0f);
        float zx = rintf(__fsub_rn(-128.0f, __fdiv_rn(lx, sx)));
        float lw = dec_f(g_mm[2]), hw = dec_f(g_mm[3]);
        float sw = __fdiv_rn(__fsub_rn(hw, lw), 255.0f);
        float zw = rintf(__fsub_rn(-128.0f, __fdiv_rn(lw, sw)));
        g_qp[0] = sx; g_qp[1] = zx; g_qp[2] = sw; g_qp[3] = zw;
        float s1x = g_cs[0],  s2x = g_cs[2];
        float s1n = g_cs[4],  s2n = g_cs[6];
        float s1wn = g_cs[8],  s2wn = g_cs[10];
        float s1wp = g_cs[12], s2wp = g_cs[14];
        g_segscale[0] = __fmul_rn(sx, sw);
        g_segscale[1] = -__fmul_rn(s1x, s1wn);
        g_segscale[2] = -__fmul_rn(s1x, s2wn);
        g_segscale[3] = -__fmul_rn(s2x, s1wn);
        g_segscale[4] = -__fmul_rn(s2x, s2wn);
        g_segscale[5] = -__fmul_rn(s1n, s1wp);
        g_segscale[6] = -__fmul_rn(s1n, s2wp);
        g_segscale[7] = -__fmul_rn(s2n, s1wp);
        g_segscale[8] = -__fmul_rn(s2n, s2wp);
    }
}

// ---------------- quantize -> int8 q, transposed to K-major + row sums ----------------
__global__ void quantT_kernel() {
    __shared__ float tile[32][33];
    int c0 = blockIdx.x * 32, k0 = blockIdx.y * 32;
    int tx = threadIdx.x, ty = threadIdx.y;
    bool isx = (c0 < BSZ);
    float s = isx ? g_qp[0] : g_qp[2];
    float z = isx ? g_qp[1] : g_qp[3];
#pragma unroll
    for (int i = ty; i < 32; i += 8) {
        float t = g_a[(size_t)(k0 + i) * COLS + c0 + tx];
        float q = rintf(__fadd_rn(__fdiv_rn(t, s), z));
        q = fminf(fmaxf(q, -128.0f), 127.0f);
        tile[i][tx] = q;
    }
    __syncthreads();
    int8_t* dst = isx ? g_qx8 : g_qw8;
    int cb = isx ? c0 : (c0 - BSZ);
#pragma unroll
    for (int i = ty; i < 32; i += 8) {
        int qi = (int)tile[tx][i];
        dst[(size_t)(cb + i) * IN_F + k0 + tx] = (int8_t)qi;
        int wsum = __reduce_add_sync(0xFFFFFFFFu, qi);
        if (tx == 0) atomicAdd(&g_sums[c0 + i], wsum);
    }
}

// ---------------- int8 TMA-fed mma.sync GEMM, 9 segments, 512 thr ----------------
// seg0:(qx,qw)+sxsw ; 1:(q1x,q1wn) 2:(q1x,q2wn) 3:(q2x,q1wn) 4:(q2x,q2wn)  (-scale)
// 5:(q1nx,q1wp) 6:(q1nx,q2wp) 7:(q2nx,q1wp) 8:(q2nx,q2wp)                  (-scale)
// epilogue: out = accf + sxsw*(-zx*Sw - zw*Sx + K*zx*zw) + bias
__global__ void __launch_bounds__(512)
gemm_s8_kernel(const __grid_constant__ TmapPack tp,
               const float* __restrict__ bias, float* __restrict__ out) {
    extern __shared__ __align__(1024) char smem[];
    uint32_t sb = smem_u32(smem);
    const int tid = threadIdx.x, lane = tid & 31, warp = tid >> 5;
    const int bn = blockIdx.x, bm = blockIdx.y;
    const int wm = (warp >> 2) * 32;   // 4 m-warps x 32 rows
    const int wn = (warp & 3) * 16;    // 4 n-warps x 16 cols

    if (tid == 0) {
#pragma unroll
        for (int i = 0; i < NSTG; i++) MBAR_INIT(sb + i * 8, 1);
    }
    __syncthreads();

    int   acc_s[2][2][4];
    float acc_f[2][2][4];
#pragma unroll
    for (int a = 0; a < 2; a++)
#pragma unroll
        for (int b = 0; b < 2; b++)
#pragma unroll
            for (int q = 0; q < 4; q++) { acc_s[a][b][q] = 0; acc_f[a][b][q] = 0.f; }

    static const int asel[NSEG] = {0, 1, 1, 2, 2, 3, 3, 4, 4};
    static const int bsel[NSEG] = {0, 1, 2, 1, 2, 3, 4, 3, 4};

    if (tid == 0) {
#pragma unroll
        for (int p = 0; p < NSTG; p++) {
            int kx = p * KCH;   // p < 4 -> seg 0
            uint32_t st = sb + 1024 + p * ST_BYTES;
            MBAR_EXPECT_TX(sb + p * 8, ST_BYTES);
            TMA_2D(st,           &tp.a[0], kx, bm * 128, sb + p * 8);
            TMA_2D(st + A_BYTES, &tp.b[0], kx, bn * 64,  sb + p * 8);
        }
    }

    for (int c = 0; c < NCH; c++) {
        int s = c & (NSTG - 1), ph = (c / NSTG) & 1;
        MBAR_WAIT(sb + s * 8, ph);
        uint32_t abase = sb + 1024 + s * ST_BYTES;
        uint32_t bbase = abase + A_BYTES;
#pragma unroll
        for (int kq = 0; kq < 4; kq++) {
            uint32_t af[2][4], bf[2][2];
#pragma unroll
            for (int mt = 0; mt < 2; mt++) {
                int row = wm + mt * 16 + (lane & 15);
                int chk = kq * 2 + (lane >> 4);
                uint32_t off = (uint32_t)(row * 128 + chk * 16);
                uint32_t ad = abase + (off ^ ((off >> 3) & 0x70));
                asm volatile("ldmatrix.sync.aligned.m8n8.x4.shared.b16 {%0,%1,%2,%3},[%4];"
                             : "=r"(af[mt][0]), "=r"(af[mt][1]), "=r"(af[mt][2]), "=r"(af[mt][3])
                             : "r"(ad));
            }
#pragma unroll
            for (int nt = 0; nt < 2; nt++) {
                int row = wn + nt * 8 + (lane & 7);
                int chk = kq * 2 + ((lane >> 3) & 1);
                uint32_t off = (uint32_t)(row * 128 + chk * 16);
                uint32_t bd = bbase + (off ^ ((off >> 3) & 0x70));
                asm volatile("ldmatrix.sync.aligned.m8n8.x2.shared.b16 {%0,%1},[%2];"
                             : "=r"(bf[nt][0]), "=r"(bf[nt][1]) : "r"(bd));
            }
#pragma unroll
            for (int mt = 0; mt < 2; mt++)
#pragma unroll
                for (int nt = 0; nt < 2; nt++) {
                    asm volatile(
                        "mma.sync.aligned.m16n8k32.row.col.s32.s8.s8.s32 "
                        "{%0,%1,%2,%3},{%4,%5,%6,%7},{%8,%9},{%0,%1,%2,%3};"
                        : "+r"(acc_s[mt][nt][0]), "+r"(acc_s[mt][nt][1]),
                          "+r"(acc_s[mt][nt][2]), "+r"(acc_s[mt][nt][3])
                        : "r"(af[mt][0]), "r"(af[mt][1]), "r"(af[mt][2]), "r"(af[mt][3]),
                          "r"(bf[nt][0]), "r"(bf[nt][1]));
                }
        }
        if ((c & (CHPS - 1)) == CHPS - 1) {   // segment boundary: fold scale
            float f = g_segscale[c >> 5];     // L2-resident, no local array
#pragma unroll
            for (int a = 0; a < 2; a++)
#pragma unroll
                for (int b = 0; b < 2; b++)
#pragma unroll
                    for (int q = 0; q < 4; q++) {
                        acc_f[a][b][q] = __fmaf_rn(f, __int2float_rn(acc_s[a][b][q]), acc_f[a][b][q]);
                        acc_s[a][b][q] = 0;
                    }
        }
        __syncthreads();
        if (tid == 0 && c + NSTG < NCH) {
            int nc = c + NSTG;
            int seg = nc >> 5, kx = (nc & (CHPS - 1)) * KCH;
            uint32_t st = sb + 1024 + s * ST_BYTES;
            MBAR_EXPECT_TX(sb + s * 8, ST_BYTES);
            TMA_2D(st,           &tp.a[asel[seg]], kx, bm * 128, sb + s * 8);
            TMA_2D(st + A_BYTES, &tp.b[bsel[seg]], kx, bn * 64,  sb + s * 8);
        }
    }

    // epilogue
    const float sxsw = __fmul_rn(g_qp[0], g_qp[2]);
    const float zx = g_qp[1], zw = g_qp[3];
    const float kzz = __fmul_rn(4096.0f, __fmul_rn(zx, zw));
    const int grp = lane >> 2, tig = lane & 3;
#pragma unroll
    for (int mt = 0; mt < 2; mt++)
#pragma unroll
        for (int nt = 0; nt < 2; nt++) {
            int gm = bm * 128 + wm + mt * 16 + grp;
            int gn = bn * 64 + wn + nt * 8 + tig * 2;
            float Sx0 = (float)g_sums[gm], Sx1 = (float)g_sums[gm + 8];
            float Sw0 = (float)g_sums[BSZ + gn], Sw1 = (float)g_sums[BSZ + gn + 1];
            float b0 = bias[gn], b1 = bias[gn + 1];
            float R00 = __fmul_rn(sxsw, __fmaf_rn(-zx, Sw0, __fmaf_rn(-zw, Sx0, kzz)));
            float R01 = __fmul_rn(sxsw, __fmaf_rn(-zx, Sw1, __fmaf_rn(-zw, Sx0, kzz)));
            float R10 = __fmul_rn(sxsw, __fmaf_rn(-zx, Sw0, __fmaf_rn(-zw, Sx1, kzz)));
            float R11 = __fmul_rn(sxsw, __fmaf_rn(-zx, Sw1, __fmaf_rn(-zw, Sx1, kzz)));
            float2 v0, v1;
            v0.x = __fadd_rn(__fadd_rn(acc_f[mt][nt][0], R00), b0);
            v0.y = __fadd_rn(__fadd_rn(acc_f[mt][nt][1], R01), b1);
            v1.x = __fadd_rn(__fadd_rn(acc_f[mt][nt][2], R10), b0);
            v1.y = __fadd_rn(__fadd_rn(acc_f[mt][nt][3], R11), b1);
            *(float2*)&out[(size_t)gm * OUT_F + gn]       = v0;
            *(float2*)&out[(size_t)(gm + 8) * OUT_F + gn] = v1;
        }
}

// ---------------- host ----------------
typedef CUresult (*EncodeFn)(CUtensorMap*, CUtensorMapDataType, cuuint32_t, void*,
                             const cuuint64_t*, const cuuint64_t*, const cuuint32_t*,
                             const cuuint32_t*, CUtensorMapInterleave, CUtensorMapSwizzle,
                             CUtensorMapL2promotion, CUtensorMapFloatOOBfill);

static void encode_map(EncodeFn enc, CUtensorMap* m, void* ptr, int rows, int boxrows) {
    cuuint64_t dims[2]    = {(cuuint64_t)IN_F, (cuuint64_t)rows};
    cuuint64_t strides[1] = {(cuuint64_t)IN_F};
    cuuint32_t box[2]     = {(cuuint32_t)KCH, (cuuint32_t)boxrows};
    cuuint32_t estr[2]    = {1, 1};
    enc(m, CU_TENSOR_MAP_DATA_TYPE_UINT8, 2, ptr, dims, strides, box, estr,
        CU_TENSOR_MAP_INTERLEAVE_NONE, CU_TENSOR_MAP_SWIZZLE_128B,
        CU_TENSOR_MAP_L2_PROMOTION_L2_128B, CU_TENSOR_MAP_FLOAT_OOB_FILL_NONE);
}

extern "C" void kernel_launch(void* const* d_in, const int* in_sizes, int n_in,
                              void* d_out, int out_size) {
    const float* x    = (const float*)d_in[0];
    const float* wgt  = (const float*)d_in[1];
    const float* bias = (const float*)d_in[2];
    const float* wn   = (const float*)d_in[3];
    const float* nx   = (const float*)d_in[4];
    const int*   perms= (const int*)  d_in[5];
    const float* mats = (const float*)d_in[6];
    float* out = (float*)d_out;

    make_wmats_kernel<<<(ROUNDS * GROUPS + 255) / 256, 256>>>(mats);
    reset_kernel<<<(COLS + 255) / 256, 256>>>();
    maxabs_x_kernel<<<1024, 256>>>(x, nx);
    maxabs_w_kernel<<<256, 256>>>(wgt, wn);
    scalesA_kernel<<<1, 32>>>();

    prepsplit_x_kernel<<<dim3(BSZ / 32, IN_F / 32), dim3(32, 8)>>>(x, nx);
    prepsplit_w_kernel<<<dim3(OUT_F / 32, IN_F / 32), dim3(32, 8)>>>(wgt, wn);

    for (int p = 0; p < ROUNDS / 2; p++) {
        int r = 2 * p;
        round2_kernel<<<dim3(COLS4 / 256, GROUPS), 256>>>(
            p & 1, r,
            perms + (size_t)r * IN_F, perms + (size_t)(r + 1) * IN_F,
            mats + (size_t)r * GROUPS * 4, mats + (size_t)(r + 1) * GROUPS * 4,
            (p == ROUNDS / 2 - 1) ? 1 : 0);
    }

    qparams_kernel<<<1, 32>>>();
    quantT_kernel<<<dim3(COLS / 32, IN_F / 32), dim3(32, 8)>>>();

    void* fp = nullptr;
#if CUDART_VERSION >= 12050
    cudaDriverEntryPointQueryResult qr;
    cudaGetDriverEntryPointByVersion("cuTensorMapEncodeTiled", &fp, 12000,
                                     cudaEnableDefault, &qr);
#else
    cudaGetDriverEntryPoint("cuTensorMapEncodeTiled", &fp, cudaEnableDefault);
#endif
    EncodeFn enc = (EncodeFn)fp;

    void *pa0, *pa1, *pa2, *pa3, *pa4, *pb0, *pb1, *pb2, *pb3, *pb4;
    cudaGetSymbolAddress(&pa0, g_qx8);  cudaGetSymbolAddress(&pa1, g_q1x);
    cudaGetSymbolAddress(&pa2, g_q2x);  cudaGetSymbolAddress(&pa3, g_q1nx);
    cudaGetSymbolAddress(&pa4, g_q2nx); cudaGetSymbolAddress(&pb0, g_qw8);
    cudaGetSymbolAddress(&pb1, g_q1wn); cudaGetSymbolAddress(&pb2, g_q2wn);
    cudaGetSymbolAddress(&pb3, g_q1wp); cudaGetSymbolAddress(&pb4, g_q2wp);

    TmapPack tp;
    encode_map(enc, &tp.a[0], pa0, BSZ,   128);
    encode_map(enc, &tp.a[1], pa1, BSZ,   128);
    encode_map(enc, &tp.a[2], pa2, BSZ,   128);
    encode_map(enc, &tp.a[3], pa3, BSZ,   128);
    encode_map(enc, &tp.a[4], pa4, BSZ,   128);
    encode_map(enc, &tp.b[0], pb0, OUT_F, 64);
    encode_map(enc, &tp.b[1], pb1, OUT_F, 64);
    encode_map(enc, &tp.b[2], pb2, OUT_F, 64);
    encode_map(enc, &tp.b[3], pb3, OUT_F, 64);
    encode_map(enc, &tp.b[4], pb4, OUT_F, 64);

    cudaFuncSetAttribute(gemm_s8_kernel, cudaFuncAttributeMaxDynamicSharedMemorySize, DSMEM);
    gemm_s8_kernel<<<dim3(OUT_F / 64, BSZ / 128), 512, DSMEM>>>(tp, bias, out);
}

// round 14
// speedup vs baseline: 2.5240x; 2.5240x over previous
#include <cuda_runtime.h>
#include <cuda.h>
#include <cuda_bf16.h>
#include <math.h>
#include <stdint.h>

#define IN_F   4096
#define OUT_F  1024
#define BSZ    8192
#define COLS   9216
#define COLS4  2304
#define GROUPS 2048
#define ROUNDS 12

#define KCH    64
#define CHPS   64             // chunks per segment
#define NSEG   7
#define NCH    (NSEG * CHPS)  // 448
#define NSTG   3
#define A_BYTES 32768         // 256 x 64 bf16
#define B_BYTES 16384         // 128 x 64 bf16
#define ST_BYTES (A_BYTES + B_BYTES)
#define DSMEM (1024 + NSTG * ST_BYTES)   // 148480

// ---------------- device scratch ----------------
__device__ __align__(128) float g_a[(size_t)IN_F * COLS];
__device__ __align__(128) float g_b[(size_t)IN_F * COLS];
__device__ __align__(128) float g_wmats[ROUNDS * GROUPS * 4];
__device__ unsigned g_mm[4];
__device__ float    g_qp[4];

__device__ __align__(128) __nv_bfloat16 g_qx  [(size_t)BSZ   * IN_F];
__device__ __align__(128) __nv_bfloat16 g_qw  [(size_t)OUT_F * IN_F];
__device__ __align__(128) __nv_bfloat16 g_xhi [(size_t)BSZ   * IN_F];
__device__ __align__(128) __nv_bfloat16 g_xlo [(size_t)BSZ   * IN_F];
__device__ __align__(128) __nv_bfloat16 g_nxhi[(size_t)BSZ   * IN_F];
__device__ __align__(128) __nv_bfloat16 g_nxlo[(size_t)BSZ   * IN_F];
__device__ __align__(128) __nv_bfloat16 g_wnhi[(size_t)OUT_F * IN_F];
__device__ __align__(128) __nv_bfloat16 g_wnlo[(size_t)OUT_F * IN_F];
__device__ __align__(128) __nv_bfloat16 g_wphi[(size_t)OUT_F * IN_F];
__device__ __align__(128) __nv_bfloat16 g_wplo[(size_t)OUT_F * IN_F];

struct TmapPack { CUtensorMap a[5]; CUtensorMap b[5]; };

// ---------------- helpers ----------------
__device__ __forceinline__ unsigned enc_f(float f) {
    unsigned u = __float_as_uint(f);
    return (u & 0x80000000u) ? ~u : (u | 0x80000000u);
}
__device__ __forceinline__ float dec_f(unsigned k) {
    return __uint_as_float((k & 0x80000000u) ? (k ^ 0x80000000u) : ~k);
}
__device__ __forceinline__ uint32_t smem_u32(const void* p) {
    uint32_t a;
    asm("{ .reg .u64 t; cvta.to.shared.u64 t, %1; cvt.u32.u64 %0, t; }" : "=r"(a) : "l"(p));
    return a;
}
__device__ __forceinline__ void split1(float v, __nv_bfloat16& h, __nv_bfloat16& l) {
    h = __float2bfloat16_rn(v);
    l = __float2bfloat16_rn(__fsub_rn(v, __bfloat162float(h)));
}

#define MBAR_INIT(addr, cnt) \
    asm volatile("mbarrier.init.shared.b64 [%0], %1;" :: "r"(addr), "r"(cnt) : "memory")
#define MBAR_EXPECT_TX(addr, bytes) \
    asm volatile("mbarrier.arrive.expect_tx.shared.b64 _, [%0], %1;" :: "r"(addr), "r"(bytes) : "memory")
#define MBAR_WAIT(addr, par) do {                                              \
    asm volatile(                                                              \
        "{\n\t.reg .pred P;\n\t"                                               \
        "WL_%=:\n\t"                                                           \
        "mbarrier.try_wait.parity.acquire.cta.shared::cta.b64 P, [%0], %1, 0x989680;\n\t" \
        "@P bra.uni WD_%=;\n\t"                                                \
        "bra.uni WL_%=;\n\t"                                                   \
        "WD_%=:\n\t}"                                                          \
        :: "r"(addr), "r"(par) : "memory");                                    \
} while (0)

#define TMA_2D(smem, map, cx, cy, mbar) \
    asm volatile("cp.async.bulk.tensor.2d.shared::cta.global.tile.mbarrier::complete_tx::bytes " \
                 "[%0], [%1, {%2, %3}], [%4];" \
                 :: "r"(smem), "l"(map), "r"(cx), "r"(cy), "r"(mbar) : "memory")

// ---------------- inv(m)^T via LU w/ partial pivoting ----------------
__global__ void make_wmats_kernel(const float* __restrict__ mats) {
    int idx = blockIdx.x * blockDim.x + threadIdx.x;
    if (idx >= ROUNDS * GROUPS) return;
    const float* m = mats + (size_t)idx * 4;
    float a = m[0], b = m[1], c = m[2], d = m[3];
    float i00, i01, i10, i11;
    if (fabsf(c) > fabsf(a)) {
        float l   = __fdiv_rn(a, c);
        float u22 = __fmaf_rn(-l, d, b);
        float x2c1 = __fdiv_rn(1.0f, u22);
        float x1c1 = __fdiv_rn(__fmul_rn(-d, x2c1), c);
        float x2c2 = __fdiv_rn(-l, u22);
        float x1c2 = __fdiv_rn(__fmaf_rn(-d, x2c2, 1.0f), c);
        i00 = x1c1; i01 = x1c2; i10 = x2c1; i11 = x2c2;
    } else {
        float l   = __fdiv_rn(c, a);
        float u22 = __fmaf_rn(-l, b, d);
        float x2c1 = __fdiv_rn(-l, u22);
        float x1c1 = __fdiv_rn(__fmaf_rn(-b, x2c1, 1.0f), a);
        float x2c2 = __fdiv_rn(1.0f, u22);
        float x1c2 = __fdiv_rn(__fmul_rn(-b, x2c2), a);
        i00 = x1c1; i01 = x1c2; i10 = x2c1; i11 = x2c2;
    }
    float* o = g_wmats + (size_t)idx * 4;
    o[0] = i00; o[1] = i10; o[2] = i01; o[3] = i11;
}

// ---------------- fused transpose+add + bf16 splits ----------------
__global__ void prepsplit_x_kernel(const float* __restrict__ x, const float* __restrict__ nx) {
    __shared__ float tile[32][33];
    int c0 = blockIdx.x * 32, k0 = blockIdx.y * 32;
    int tx = threadIdx.x, ty = threadIdx.y;
#pragma unroll
    for (int i = ty; i < 32; i += 8) {
        size_t idx = (size_t)(c0 + i) * IN_F + k0 + tx;
        float vx = x[idx], vn = nx[idx];
        tile[i][tx] = __fadd_rn(vx, vn);
        __nv_bfloat16 h, l;
        split1(vx, h, l); g_xhi[idx]  = h; g_xlo[idx]  = l;
        split1(vn, h, l); g_nxhi[idx] = h; g_nxlo[idx] = l;
    }
    __syncthreads();
#pragma unroll
    for (int i = ty; i < 32; i += 8)
        g_a[(size_t)(k0 + i) * COLS + c0 + tx] = tile[tx][i];
}
__global__ void prepsplit_w_kernel(const float* __restrict__ w, const float* __restrict__ wn) {
    __shared__ float tile[32][33];
    int c0 = blockIdx.x * 32, k0 = blockIdx.y * 32;
    int tx = threadIdx.x, ty = threadIdx.y;
#pragma unroll
    for (int i = ty; i < 32; i += 8) {
        size_t idx = (size_t)(c0 + i) * IN_F + k0 + tx;
        float vw = w[idx], vn = wn[idx];
        float vp = __fadd_rn(vw, vn);
        tile[i][tx] = vp;
        __nv_bfloat16 h, l;
        split1(vn, h, l); g_wnhi[idx] = h; g_wnlo[idx] = l;
        split1(vp, h, l); g_wphi[idx] = h; g_wplo[idx] = l;
    }
    __syncthreads();
#pragma unroll
    for (int i = ty; i < 32; i += 8)
        g_a[(size_t)(k0 + i) * COLS + BSZ + c0 + tx] = tile[tx][i];
}

// ---------------- THREE fused permutation + 2x2-mix rounds (bitwise-exact, NO FMA) ----
// out pair g (round r+2) <- 2 level-1 rows <- 4 level-0 rows <- 8 input rows.
// Each level computed with the reference's exact rn(rn(c0*a)+rn(c1*b)) order.
__device__ __forceinline__ float4 mix4(float c0, float c1, float4 A, float4 B) {
    float4 z;
    z.x = __fadd_rn(__fmul_rn(c0, A.x), __fmul_rn(c1, B.x));
    z.y = __fadd_rn(__fmul_rn(c0, A.y), __fmul_rn(c1, B.y));
    z.z = __fadd_rn(__fmul_rn(c0, A.z), __fmul_rn(c1, B.z));
    z.w = __fadd_rn(__fmul_rn(c0, A.w), __fmul_rn(c1, B.w));
    return z;
}
__global__ void round3_kernel(int dir, int r,
                              const int* __restrict__ p0,
                              const int* __restrict__ p1,
                              const int* __restrict__ p2,
                              const float* __restrict__ mx0,
                              const float* __restrict__ mx1,
                              const float* __restrict__ mx2,
                              int do_mm) {
    const float* in  = dir ? g_b : g_a;
    float*       out = dir ? g_a : g_b;
    int g   = blockIdx.y;
    int col = blockIdx.x * 256 + threadIdx.x;
    bool isx = (col < BSZ / 4);
    const float* M0 = isx ? mx0 : (g_wmats + (size_t)(r + 0) * GROUPS * 4);
    const float* M1 = isx ? mx1 : (g_wmats + (size_t)(r + 1) * GROUPS * 4);
    const float* M2 = isx ? mx2 : (g_wmats + (size_t)(r + 2) * GROUPS * 4);

    int ia = __ldg(&p2[2 * g]), ib = __ldg(&p2[2 * g + 1]);
    int ga = ia >> 1, pa = ia & 1;
    int gb = ib >> 1, pb = ib & 1;
    int ja0 = __ldg(&p1[2 * ga]), ja1 = __ldg(&p1[2 * ga + 1]);
    int jb0 = __ldg(&p1[2 * gb]), jb1 = __ldg(&p1[2 * gb + 1]);

    // level 0: z_j for j in {ja0, ja1, jb0, jb1}
    float4 z[4];
    int js[4] = {ja0, ja1, jb0, jb1};
#pragma unroll
    for (int t = 0; t < 4; t++) {
        int j = js[t];
        int gj = j >> 1, pj = j & 1;
        int r0 = __ldg(&p0[2 * gj]), r1 = __ldg(&p0[2 * gj + 1]);
        float4 Mj = __ldg((const float4*)(M0 + (size_t)gj * 4));
        float c0 = pj ? Mj.z : Mj.x, c1 = pj ? Mj.w : Mj.y;
        float4 A = ((const float4*)(in + (size_t)r0 * COLS))[col];
        float4 B = ((const float4*)(in + (size_t)r1 * COLS))[col];
        z[t] = mix4(c0, c1, A, B);
    }
    // level 1
    float4 Ma = __ldg((const float4*)(M1 + (size_t)ga * 4));
    float4 Mb = __ldg((const float4*)(M1 + (size_t)gb * 4));
    float ca0 = pa ? Ma.z : Ma.x, ca1 = pa ? Ma.w : Ma.y;
    float cb0 = pb ? Mb.z : Mb.x, cb1 = pb ? Mb.w : Mb.y;
    float4 ya = mix4(ca0, ca1, z[0], z[1]);
    float4 yb = mix4(cb0, cb1, z[2], z[3]);
    // level 2
    float4 Mg = __ldg((const float4*)(M2 + (size_t)g * 4));
    float4 o0 = mix4(Mg.x, Mg.y, ya, yb);
    float4 o1 = mix4(Mg.z, Mg.w, ya, yb);
    ((float4*)(out + (size_t)(2 * g)     * COLS))[col] = o0;
    ((float4*)(out + (size_t)(2 * g + 1) * COLS))[col] = o1;

    if (do_mm) {   // block uniformly x (blocks 0-7) or w (block 8)
        float lo = fminf(fminf(fminf(o0.x, o0.y), fminf(o0.z, o0.w)),
                         fminf(fminf(o1.x, o1.y), fminf(o1.z, o1.w)));
        float hi = fmaxf(fmaxf(fmaxf(o0.x, o0.y), fmaxf(o0.z, o0.w)),
                         fmaxf(fmaxf(o1.x, o1.y), fmaxf(o1.z, o1.w)));
        __shared__ float red[256];
        red[threadIdx.x] = lo; __syncthreads();
        for (int s = 128; s > 0; s >>= 1) {
            if (threadIdx.x < s) red[threadIdx.x] = fminf(red[threadIdx.x], red[threadIdx.x + s]);
            __syncthreads();
        }
        if (threadIdx.x == 0) atomicMin(&g_mm[isx ? 0 : 2], enc_f(red[0]));
        __syncthreads();
        red[threadIdx.x] = hi; __syncthreads();
        for (int s = 128; s > 0; s >>= 1) {
            if (threadIdx.x < s) red[threadIdx.x] = fmaxf(red[threadIdx.x], red[threadIdx.x + s]);
            __syncthreads();
        }
        if (threadIdx.x == 0) atomicMax(&g_mm[isx ? 1 : 3], enc_f(red[0]));
    }
}

// ---------------- reset + qparams ----------------
__global__ void reset_kernel() {
    if (threadIdx.x == 0) {
        g_mm[0] = 0xFFFFFFFFu; g_mm[1] = 0u;
        g_mm[2] = 0xFFFFFFFFu; g_mm[3] = 0u;
    }
}
__global__ void qparams_kernel() {
    if (threadIdx.x == 0) {
        float lx = dec_f(g_mm[0]), hx = dec_f(g_mm[1]);
        float sx = __fdiv_rn(__fsub_rn(hx, lx), 255.0f);
        float zx = rintf(__fsub_rn(-128.0f, __fdiv_rn(lx, sx)));
        float lw = dec_f(g_mm[2]), hw = dec_f(g_mm[3]);
        float sw = __fdiv_rn(__fsub_rn(hw, lw), 255.0f);
        float zw = rintf(__fsub_rn(-128.0f, __fdiv_rn(lw, sw)));
        g_qp[0] = sx; g_qp[1] = zx; g_qp[2] = sw; g_qp[3] = zw;
    }
}

// ---------------- quantize -> integer (q - zp) bf16, K-major ----------------
__global__ void quantT_kernel() {
    __shared__ float tile[32][33];
    int c0 = blockIdx.x * 32, k0 = blockIdx.y * 32;
    int tx = threadIdx.x, ty = threadIdx.y;
    bool isx = (c0 < BSZ);
    float s = isx ? g_qp[0] : g_qp[2];
    float z = isx ? g_qp[1] : g_qp[3];
#pragma unroll
    for (int i = ty; i < 32; i += 8) {
        float t = g_a[(size_t)(k0 + i) * COLS + c0 + tx];
        float q = rintf(__fadd_rn(__fdiv_rn(t, s), z));
        q = fminf(fmaxf(q, -128.0f), 127.0f);
        tile[i][tx] = __fsub_rn(q, z);
    }
    __syncthreads();
    __nv_bfloat16* dst = isx ? g_qx : g_qw;
    int cb = isx ? c0 : (c0 - BSZ);
#pragma unroll
    for (int i = ty; i < 32; i += 8) {
        dst[(size_t)(cb + i) * IN_F + k0 + tx] = __float2bfloat16_rn(tile[tx][i]);
    }
}

// ---------------- TMA-fed mma.sync GEMM, tile 256x128 (proven R10) ----------------
// segs: 0:(qx,qw) ; 1..6: (xhi,wnhi)(xhi,wnlo)(xlo,wnhi)(nxhi,wphi)(nxhi,wplo)(nxlo,wphi)
// acc = Sum_q ; at seg0 end acc *= -sx*sw ; then acc += corr ; out = bias - acc
__global__ void __launch_bounds__(512)
gemm_tma_kernel(const __grid_constant__ TmapPack tp,
                const float* __restrict__ bias, float* __restrict__ out) {
    extern __shared__ __align__(1024) char smem[];
    uint32_t sb = smem_u32(smem);
    const int tid = threadIdx.x, lane = tid & 31, warp = tid >> 5;
    const int bn = blockIdx.x, bm = blockIdx.y;
    const int wm = (warp >> 2) * 64, wn = (warp & 3) * 32;

    if (tid == 0) {
#pragma unroll
        for (int i = 0; i < NSTG; i++) MBAR_INIT(sb + i * 8, 1);
    }
    __syncthreads();

    float acc[4][4][4];
#pragma unroll
    for (int a = 0; a < 4; a++)
#pragma unroll
        for (int b = 0; b < 4; b++)
#pragma unroll
            for (int c = 0; c < 4; c++) acc[a][b][c] = 0.0f;

    const float nss = -__fmul_rn(g_qp[0], g_qp[2]);

    static const int asel[NSEG] = {0, 1, 1, 2, 3, 3, 4};
    static const int bsel[NSEG] = {0, 1, 2, 1, 3, 4, 3};

    if (tid == 0) {
#pragma unroll
        for (int p = 0; p < NSTG; p++) {
            int kx = p * KCH;   // p < 3 -> seg 0
            uint32_t st = sb + 1024 + p * ST_BYTES;
            MBAR_EXPECT_TX(sb + p * 8, ST_BYTES);
            TMA_2D(st,           &tp.a[0], kx, bm * 256, sb + p * 8);
            TMA_2D(st + A_BYTES, &tp.b[0], kx, bn * 128, sb + p * 8);
        }
    }

    for (int c = 0; c < NCH; c++) {
        int s = c % NSTG, ph = (c / NSTG) & 1;
        MBAR_WAIT(sb + s * 8, ph);
        uint32_t abase = sb + 1024 + s * ST_BYTES;
        uint32_t bbase = abase + A_BYTES;
#pragma unroll
        for (int kq = 0; kq < 4; kq++) {
            uint32_t af[4][4], bf[4][2];
#pragma unroll
            for (int mt = 0; mt < 4; mt++) {
                int row = wm + mt * 16 + (lane & 15);
                int chk = kq * 2 + (lane >> 4);
                uint32_t off = (uint32_t)(row * 128 + chk * 16);
                uint32_t ad = abase + (off ^ ((off >> 3) & 0x70));
                asm volatile("ldmatrix.sync.aligned.m8n8.x4.shared.b16 {%0,%1,%2,%3},[%4];"
                             : "=r"(af[mt][0]), "=r"(af[mt][1]), "=r"(af[mt][2]), "=r"(af[mt][3])
                             : "r"(ad));
            }
#pragma unroll
            for (int nt = 0; nt < 4; nt++) {
                int row = wn + nt * 8 + (lane & 7);
                int chk = kq * 2 + ((lane >> 3) & 1);
                uint32_t off = (uint32_t)(row * 128 + chk * 16);
                uint32_t bd = bbase + (off ^ ((off >> 3) & 0x70));
                asm volatile("ldmatrix.sync.aligned.m8n8.x2.shared.b16 {%0,%1},[%2];"
                             : "=r"(bf[nt][0]), "=r"(bf[nt][1]) : "r"(bd));
            }
#pragma unroll
            for (int mt = 0; mt < 4; mt++)
#pragma unroll
                for (int nt = 0; nt < 4; nt++) {
                    asm volatile(
                        "mma.sync.aligned.m16n8k16.row.col.f32.bf16.bf16.f32 "
                        "{%0,%1,%2,%3},{%4,%5,%6,%7},{%8,%9},{%0,%1,%2,%3};"
                        : "+f"(acc[mt][nt][0]), "+f"(acc[mt][nt][1]),
                          "+f"(acc[mt][nt][2]), "+f"(acc[mt][nt][3])
                        : "r"(af[mt][0]), "r"(af[mt][1]), "r"(af[mt][2]), "r"(af[mt][3]),
                          "r"(bf[nt][0]), "r"(bf[nt][1]));
                }
        }
        if (c == CHPS - 1) {
#pragma unroll
            for (int a = 0; a < 4; a++)
#pragma unroll
                for (int b = 0; b < 4; b++)
#pragma unroll
                    for (int q = 0; q < 4; q++) acc[a][b][q] = __fmul_rn(acc[a][b][q], nss);
        }
        __syncthreads();
        if (tid == 0 && c + NSTG < NCH) {
            int nc = c + NSTG;
            int seg = nc >> 6, kx = (nc & 63) * KCH;
            uint32_t st = sb + 1024 + s * ST_BYTES;
            MBAR_EXPECT_TX(sb + s * 8, ST_BYTES);
            TMA_2D(st,           &tp.a[asel[seg]], kx, bm * 256, sb + s * 8);
            TMA_2D(st + A_BYTES, &tp.b[bsel[seg]], kx, bn * 128, sb + s * 8);
        }
    }

    // epilogue: out = bias - acc
    const int grp = lane >> 2, tig = lane & 3;
#pragma unroll
    for (int mt = 0; mt < 4; mt++)
#pragma unroll
        for (int nt = 0; nt < 4; nt++) {
            int gm = bm * 256 + wm + mt * 16 + grp;
            int gn = bn * 128 + wn + nt * 8 + tig * 2;
            float b0 = bias[gn], b1 = bias[gn + 1];
            float2 v0, v1;
            v0.x = __fsub_rn(b0, acc[mt][nt][0]);
            v0.y = __fsub_rn(b1, acc[mt][nt][1]);
            v1.x = __fsub_rn(b0, acc[mt][nt][2]);
            v1.y = __fsub_rn(b1, acc[mt][nt][3]);
            *(float2*)&out[(size_t)gm * OUT_F + gn]       = v0;
            *(float2*)&out[(size_t)(gm + 8) * OUT_F + gn] = v1;
        }
}

// ---------------- host: tensormap construction ----------------
typedef CUresult (*EncodeFn)(CUtensorMap*, CUtensorMapDataType, cuuint32_t, void*,
                             const cuuint64_t*, const cuuint64_t*, const cuuint32_t*,
                             const cuuint32_t*, CUtensorMapInterleave, CUtensorMapSwizzle,
                             CUtensorMapL2promotion, CUtensorMapFloatOOBfill);

static void encode_map(EncodeFn enc, CUtensorMap* m, void* ptr, int rows, int boxrows) {
    cuuint64_t dims[2]    = {(cuuint64_t)IN_F, (cuuint64_t)rows};
    cuuint64_t strides[1] = {(cuuint64_t)IN_F * 2};
    cuuint32_t box[2]     = {(cuuint32_t)KCH, (cuuint32_t)boxrows};
    cuuint32_t estr[2]    = {1, 1};
    enc(m, CU_TENSOR_MAP_DATA_TYPE_BFLOAT16, 2, ptr, dims, strides, box, estr,
        CU_TENSOR_MAP_INTERLEAVE_NONE, CU_TENSOR_MAP_SWIZZLE_128B,
        CU_TENSOR_MAP_L2_PROMOTION_L2_128B, CU_TENSOR_MAP_FLOAT_OOB_FILL_NONE);
}

extern "C" void kernel_launch(void* const* d_in, const int* in_sizes, int n_in,
                              void* d_out, int out_size) {
    const float* x    = (const float*)d_in[0];
    const float* wgt  = (const float*)d_in[1];
    const float* bias = (const float*)d_in[2];
    const float* wn   = (const float*)d_in[3];
    const float* nx   = (const float*)d_in[4];
    const int*   perms= (const int*)  d_in[5];
    const float* mats = (const float*)d_in[6];
    float* out = (float*)d_out;

    make_wmats_kernel<<<(ROUNDS * GROUPS + 255) / 256, 256>>>(mats);
    reset_kernel<<<1, 32>>>();

    prepsplit_x_kernel<<<dim3(BSZ / 32, IN_F / 32), dim3(32, 8)>>>(x, nx);
    prepsplit_w_kernel<<<dim3(OUT_F / 32, IN_F / 32), dim3(32, 8)>>>(wgt, wn);

    // 4 fused passes (3 rounds each); last pass also does min/max
    for (int p = 0; p < ROUNDS / 3; p++) {
        int r = 3 * p;
        round3_kernel<<<dim3(COLS4 / 256, GROUPS), 256>>>(
            p & 1, r,
            perms + (size_t)(r + 0) * IN_F,
            perms + (size_t)(r + 1) * IN_F,
            perms + (size_t)(r + 2) * IN_F,
            mats + (size_t)(r + 0) * GROUPS * 4,
            mats + (size_t)(r + 1) * GROUPS * 4,
            mats + (size_t)(r + 2) * GROUPS * 4,
            (p == ROUNDS / 3 - 1) ? 1 : 0);
    }

    qparams_kernel<<<1, 32>>>();
    quantT_kernel<<<dim3(COLS / 32, IN_F / 32), dim3(32, 8)>>>();

    void* fp = nullptr;
#if CUDART_VERSION >= 12050
    cudaDriverEntryPointQueryResult qr;
    cudaGetDriverEntryPointByVersion("cuTensorMapEncodeTiled", &fp, 12000,
                                     cudaEnableDefault, &qr);
#else
    cudaGetDriverEntryPoint("cuTensorMapEncodeTiled", &fp, cudaEnableDefault);
#endif
    EncodeFn enc = (EncodeFn)fp;

    void *p_qx, *p_xhi, *p_xlo, *p_nxhi, *p_nxlo, *p_qw, *p_wnhi, *p_wnlo, *p_wphi, *p_wplo;
    cudaGetSymbolAddress(&p_qx, g_qx);     cudaGetSymbolAddress(&p_xhi, g_xhi);
    cudaGetSymbolAddress(&p_xlo, g_xlo);   cudaGetSymbolAddress(&p_nxhi, g_nxhi);
    cudaGetSymbolAddress(&p_nxlo, g_nxlo); cudaGetSymbolAddress(&p_qw, g_qw);
    cudaGetSymbolAddress(&p_wnhi, g_wnhi); cudaGetSymbolAddress(&p_wnlo, g_wnlo);
    cudaGetSymbolAddress(&p_wphi, g_wphi); cudaGetSymbolAddress(&p_wplo, g_wplo);

    TmapPack tp;
    encode_map(enc, &tp.a[0], p_qx,   BSZ,   256);
    encode_map(enc, &tp.a[1], p_xhi,  BSZ,   256);
    encode_map(enc, &tp.a[2], p_xlo,  BSZ,   256);
    encode_map(enc, &tp.a[3], p_nxhi, BSZ,   256);
    encode_map(enc, &tp.a[4], p_nxlo, BSZ,   256);
    encode_map(enc, &tp.b[0], p_qw,   OUT_F, 128);
    encode_map(enc, &tp.b[1], p_wnhi, OUT_F, 128);
    encode_map(enc, &tp.b[2], p_wnlo, OUT_F, 128);
    encode_map(enc, &tp.b[3], p_wphi, OUT_F, 128);
    encode_map(enc, &tp.b[4], p_wplo, OUT_F, 128);

    cudaFuncSetAttribute(gemm_tma_kernel, cudaFuncAttributeMaxDynamicSharedMemorySize, DSMEM);
    gemm_tma_kernel<<<dim3(OUT_F / 128, BSZ / 256), 512, DSMEM>>>(tp, bias, out);
}

// round 15
// speedup vs baseline: 3.0902x; 1.2243x over previous
#include <cuda_runtime.h>
#include <cuda.h>
#include <cuda_bf16.h>
#include <math.h>
#include <stdint.h>

#define IN_F   4096
#define OUT_F  1024
#define BSZ    8192
#define COLS   9216
#define COLS4  2304
#define GROUPS 2048
#define ROUNDS 12

#define KCH    64
#define NSEG   7
#define CHPSU  32              // chunks per segment per K-half
#define NCHU   (NSEG * CHPSU)  // 224 chunks per unit
#define NSTG   3
#define A_BYTES 16384          // 128 x 64 bf16
#define B_BYTES 16384
#define ST_BYTES (A_BYTES + B_BYTES)
#define DSMEM (1024 + NSTG * ST_BYTES)   // 99328 -> 2 CTAs/SM

// ---------------- device scratch ----------------
__device__ __align__(128) float g_a[(size_t)IN_F * COLS];
__device__ __align__(128) float g_b[(size_t)IN_F * COLS];
__device__ __align__(128) float g_wmats[ROUNDS * GROUPS * 4];
__device__ unsigned g_mm[4];
__device__ float    g_qp[4];
__device__ __align__(128) float g_p0[(size_t)BSZ * OUT_F];   // K-half partials
__device__ __align__(128) float g_p1[(size_t)BSZ * OUT_F];

__device__ __align__(128) __nv_bfloat16 g_qx  [(size_t)BSZ   * IN_F];
__device__ __align__(128) __nv_bfloat16 g_qw  [(size_t)OUT_F * IN_F];
__device__ __align__(128) __nv_bfloat16 g_xhi [(size_t)BSZ   * IN_F];
__device__ __align__(128) __nv_bfloat16 g_xlo [(size_t)BSZ   * IN_F];
__device__ __align__(128) __nv_bfloat16 g_nxhi[(size_t)BSZ   * IN_F];
__device__ __align__(128) __nv_bfloat16 g_nxlo[(size_t)BSZ   * IN_F];
__device__ __align__(128) __nv_bfloat16 g_wnhi[(size_t)OUT_F * IN_F];
__device__ __align__(128) __nv_bfloat16 g_wnlo[(size_t)OUT_F * IN_F];
__device__ __align__(128) __nv_bfloat16 g_wphi[(size_t)OUT_F * IN_F];
__device__ __align__(128) __nv_bfloat16 g_wplo[(size_t)OUT_F * IN_F];

struct TmapPack { CUtensorMap a[5]; CUtensorMap b[5]; };

// ---------------- helpers ----------------
__device__ __forceinline__ unsigned enc_f(float f) {
    unsigned u = __float_as_uint(f);
    return (u & 0x80000000u) ? ~u : (u | 0x80000000u);
}
__device__ __forceinline__ float dec_f(unsigned k) {
    return __uint_as_float((k & 0x80000000u) ? (k ^ 0x80000000u) : ~k);
}
__device__ __forceinline__ uint32_t smem_u32(const void* p) {
    uint32_t a;
    asm("{ .reg .u64 t; cvta.to.shared.u64 t, %1; cvt.u32.u64 %0, t; }" : "=r"(a) : "l"(p));
    return a;
}
__device__ __forceinline__ void split1(float v, __nv_bfloat16& h, __nv_bfloat16& l) {
    h = __float2bfloat16_rn(v);
    l = __float2bfloat16_rn(__fsub_rn(v, __bfloat162float(h)));
}

#define MBAR_INIT(addr, cnt) \
    asm volatile("mbarrier.init.shared.b64 [%0], %1;" :: "r"(addr), "r"(cnt) : "memory")
#define MBAR_EXPECT_TX(addr, bytes) \
    asm volatile("mbarrier.arrive.expect_tx.shared.b64 _, [%0], %1;" :: "r"(addr), "r"(bytes) : "memory")
#define MBAR_WAIT(addr, par) do {                                              \
    asm volatile(                                                              \
        "{\n\t.reg .pred P;\n\t"                                               \
        "WL_%=:\n\t"                                                           \
        "mbarrier.try_wait.parity.acquire.cta.shared::cta.b64 P, [%0], %1, 0x989680;\n\t" \
        "@P bra.uni WD_%=;\n\t"                                                \
        "bra.uni WL_%=;\n\t"                                                   \
        "WD_%=:\n\t}"                                                          \
        :: "r"(addr), "r"(par) : "memory");                                    \
} while (0)

#define TMA_2D(smem, map, cx, cy, mbar) \
    asm volatile("cp.async.bulk.tensor.2d.shared::cta.global.tile.mbarrier::complete_tx::bytes " \
                 "[%0], [%1, {%2, %3}], [%4];" \
                 :: "r"(smem), "l"(map), "r"(cx), "r"(cy), "r"(mbar) : "memory")

// ---------------- inv(m)^T via LU w/ partial pivoting ----------------
__global__ void make_wmats_kernel(const float* __restrict__ mats) {
    int idx = blockIdx.x * blockDim.x + threadIdx.x;
    if (idx >= ROUNDS * GROUPS) return;
    const float* m = mats + (size_t)idx * 4;
    float a = m[0], b = m[1], c = m[2], d = m[3];
    float i00, i01, i10, i11;
    if (fabsf(c) > fabsf(a)) {
        float l   = __fdiv_rn(a, c);
        float u22 = __fmaf_rn(-l, d, b);
        float x2c1 = __fdiv_rn(1.0f, u22);
        float x1c1 = __fdiv_rn(__fmul_rn(-d, x2c1), c);
        float x2c2 = __fdiv_rn(-l, u22);
        float x1c2 = __fdiv_rn(__fmaf_rn(-d, x2c2, 1.0f), c);
        i00 = x1c1; i01 = x1c2; i10 = x2c1; i11 = x2c2;
    } else {
        float l   = __fdiv_rn(c, a);
        float u22 = __fmaf_rn(-l, b, d);
        float x2c1 = __fdiv_rn(-l, u22);
        float x1c1 = __fdiv_rn(__fmaf_rn(-b, x2c1, 1.0f), a);
        float x2c2 = __fdiv_rn(1.0f, u22);
        float x1c2 = __fdiv_rn(__fmul_rn(-b, x2c2), a);
        i00 = x1c1; i01 = x1c2; i10 = x2c1; i11 = x2c2;
    }
    float* o = g_wmats + (size_t)idx * 4;
    o[0] = i00; o[1] = i10; o[2] = i01; o[3] = i11;
}

// ---------------- fused transpose+add + bf16 splits ----------------
__global__ void prepsplit_x_kernel(const float* __restrict__ x, const float* __restrict__ nx) {
    __shared__ float tile[32][33];
    int c0 = blockIdx.x * 32, k0 = blockIdx.y * 32;
    int tx = threadIdx.x, ty = threadIdx.y;
#pragma unroll
    for (int i = ty; i < 32; i += 8) {
        size_t idx = (size_t)(c0 + i) * IN_F + k0 + tx;
        float vx = x[idx], vn = nx[idx];
        tile[i][tx] = __fadd_rn(vx, vn);
        __nv_bfloat16 h, l;
        split1(vx, h, l); g_xhi[idx]  = h; g_xlo[idx]  = l;
        split1(vn, h, l); g_nxhi[idx] = h; g_nxlo[idx] = l;
    }
    __syncthreads();
#pragma unroll
    for (int i = ty; i < 32; i += 8)
        g_a[(size_t)(k0 + i) * COLS + c0 + tx] = tile[tx][i];
}
__global__ void prepsplit_w_kernel(const float* __restrict__ w, const float* __restrict__ wn) {
    __shared__ float tile[32][33];
    int c0 = blockIdx.x * 32, k0 = blockIdx.y * 32;
    int tx = threadIdx.x, ty = threadIdx.y;
#pragma unroll
    for (int i = ty; i < 32; i += 8) {
        size_t idx = (size_t)(c0 + i) * IN_F + k0 + tx;
        float vw = w[idx], vn = wn[idx];
        float vp = __fadd_rn(vw, vn);
        tile[i][tx] = vp;
        __nv_bfloat16 h, l;
        split1(vn, h, l); g_wnhi[idx] = h; g_wnlo[idx] = l;
        split1(vp, h, l); g_wphi[idx] = h; g_wplo[idx] = l;
    }
    __syncthreads();
#pragma unroll
    for (int i = ty; i < 32; i += 8)
        g_a[(size_t)(k0 + i) * COLS + BSZ + c0 + tx] = tile[tx][i];
}

// ---------------- TWO fused permutation + 2x2-mix rounds (bitwise-exact, NO FMA) ----
__global__ void round2_kernel(int dir, int r,
                              const int* __restrict__ perm0,
                              const int* __restrict__ perm1,
                              const float* __restrict__ matsx0,
                              const float* __restrict__ matsx1,
                              int do_mm) {
    const float* in  = dir ? g_b : g_a;
    float*       out = dir ? g_a : g_b;
    int g   = blockIdx.y;
    int col = blockIdx.x * 256 + threadIdx.x;
    int i0 = __ldg(&perm1[2 * g]);
    int i1 = __ldg(&perm1[2 * g + 1]);
    int g0 = i0 >> 1, p0 = i0 & 1;
    int g1 = i1 >> 1, p1 = i1 & 1;
    int ra0 = __ldg(&perm0[2 * g0]), rb0 = __ldg(&perm0[2 * g0 + 1]);
    int ra1 = __ldg(&perm0[2 * g1]), rb1 = __ldg(&perm0[2 * g1 + 1]);
    bool isx = (col < BSZ / 4);
    const float* m0base = isx ? matsx0 : (g_wmats + (size_t)r * GROUPS * 4);
    const float* m1base = isx ? matsx1 : (g_wmats + (size_t)(r + 1) * GROUPS * 4);
    float4 mA = __ldg((const float4*)(m0base + (size_t)g0 * 4));
    float4 mB = __ldg((const float4*)(m0base + (size_t)g1 * 4));
    float4 mC = __ldg((const float4*)(m1base + (size_t)g * 4));
    float c00 = p0 ? mA.z : mA.x, c01 = p0 ? mA.w : mA.y;
    float c10 = p1 ? mB.z : mB.x, c11 = p1 ? mB.w : mB.y;
    float4 a0 = ((const float4*)(in + (size_t)ra0 * COLS))[col];
    float4 b0 = ((const float4*)(in + (size_t)rb0 * COLS))[col];
    float4 a1 = ((const float4*)(in + (size_t)ra1 * COLS))[col];
    float4 b1 = ((const float4*)(in + (size_t)rb1 * COLS))[col];
    float4 v0, v1, o0, o1;
    v0.x = __fadd_rn(__fmul_rn(c00, a0.x), __fmul_rn(c01, b0.x));
    v0.y = __fadd_rn(__fmul_rn(c00, a0.y), __fmul_rn(c01, b0.y));
    v0.z = __fadd_rn(__fmul_rn(c00, a0.z), __fmul_rn(c01, b0.z));
    v0.w = __fadd_rn(__fmul_rn(c00, a0.w), __fmul_rn(c01, b0.w));
    v1.x = __fadd_rn(__fmul_rn(c10, a1.x), __fmul_rn(c11, b1.x));
    v1.y = __fadd_rn(__fmul_rn(c10, a1.y), __fmul_rn(c11, b1.y));
    v1.z = __fadd_rn(__fmul_rn(c10, a1.z), __fmul_rn(c11, b1.z));
    v1.w = __fadd_rn(__fmul_rn(c10, a1.w), __fmul_rn(c11, b1.w));
    o0.x = __fadd_rn(__fmul_rn(mC.x, v0.x), __fmul_rn(mC.y, v1.x));
    o0.y = __fadd_rn(__fmul_rn(mC.x, v0.y), __fmul_rn(mC.y, v1.y));
    o0.z = __fadd_rn(__fmul_rn(mC.x, v0.z), __fmul_rn(mC.y, v1.z));
    o0.w = __fadd_rn(__fmul_rn(mC.x, v0.w), __fmul_rn(mC.y, v1.w));
    o1.x = __fadd_rn(__fmul_rn(mC.z, v0.x), __fmul_rn(mC.w, v1.x));
    o1.y = __fadd_rn(__fmul_rn(mC.z, v0.y), __fmul_rn(mC.w, v1.y));
    o1.z = __fadd_rn(__fmul_rn(mC.z, v0.z), __fmul_rn(mC.w, v1.z));
    o1.w = __fadd_rn(__fmul_rn(mC.z, v0.w), __fmul_rn(mC.w, v1.w));
    ((float4*)(out + (size_t)(2 * g)     * COLS))[col] = o0;
    ((float4*)(out + (size_t)(2 * g + 1) * COLS))[col] = o1;

    if (do_mm) {
        float lo = fminf(fminf(fminf(o0.x, o0.y), fminf(o0.z, o0.w)),
                         fminf(fminf(o1.x, o1.y), fminf(o1.z, o1.w)));
        float hi = fmaxf(fmaxf(fmaxf(o0.x, o0.y), fmaxf(o0.z, o0.w)),
                         fmaxf(fmaxf(o1.x, o1.y), fmaxf(o1.z, o1.w)));
        __shared__ float red[256];
        red[threadIdx.x] = lo; __syncthreads();
        for (int s = 128; s > 0; s >>= 1) {
            if (threadIdx.x < s) red[threadIdx.x] = fminf(red[threadIdx.x], red[threadIdx.x + s]);
            __syncthreads();
        }
        if (threadIdx.x == 0) atomicMin(&g_mm[isx ? 0 : 2], enc_f(red[0]));
        __syncthreads();
        red[threadIdx.x] = hi; __syncthreads();
        for (int s = 128; s > 0; s >>= 1) {
            if (threadIdx.x < s) red[threadIdx.x] = fmaxf(red[threadIdx.x], red[threadIdx.x + s]);
            __syncthreads();
        }
        if (threadIdx.x == 0) atomicMax(&g_mm[isx ? 1 : 3], enc_f(red[0]));
    }
}

// ---------------- reset + qparams ----------------
__global__ void reset_kernel() {
    if (threadIdx.x == 0) {
        g_mm[0] = 0xFFFFFFFFu; g_mm[1] = 0u;
        g_mm[2] = 0xFFFFFFFFu; g_mm[3] = 0u;
    }
}
__global__ void qparams_kernel() {
    if (threadIdx.x == 0) {
        float lx = dec_f(g_mm[0]), hx = dec_f(g_mm[1]);
        float sx = __fdiv_rn(__fsub_rn(hx, lx), 255.0f);
        float zx = rintf(__fsub_rn(-128.0f, __fdiv_rn(lx, sx)));
        float lw = dec_f(g_mm[2]), hw = dec_f(g_mm[3]);
        float sw = __fdiv_rn(__fsub_rn(hw, lw), 255.0f);
        float zw = rintf(__fsub_rn(-128.0f, __fdiv_rn(lw, sw)));
        g_qp[0] = sx; g_qp[1] = zx; g_qp[2] = sw; g_qp[3] = zw;
    }
}

// ---------------- quantize -> integer (q - zp) bf16, K-major ----------------
__global__ void quantT_kernel() {
    __shared__ float tile[32][33];
    int c0 = blockIdx.x * 32, k0 = blockIdx.y * 32;
    int tx = threadIdx.x, ty = threadIdx.y;
    bool isx = (c0 < BSZ);
    float s = isx ? g_qp[0] : g_qp[2];
    float z = isx ? g_qp[1] : g_qp[3];
#pragma unroll
    for (int i = ty; i < 32; i += 8) {
        float t = g_a[(size_t)(k0 + i) * COLS + c0 + tx];
        float q = rintf(__fadd_rn(__fdiv_rn(t, s), z));
        q = fminf(fmaxf(q, -128.0f), 127.0f);
        tile[i][tx] = __fsub_rn(q, z);
    }
    __syncthreads();
    __nv_bfloat16* dst = isx ? g_qx : g_qw;
    int cb = isx ? c0 : (c0 - BSZ);
#pragma unroll
    for (int i = ty; i < 32; i += 8) {
        dst[(size_t)(cb + i) * IN_F + k0 + tx] = __float2bfloat16_rn(tile[tx][i]);
    }
}

// ---------------- TMA-fed mma.sync GEMM, tile 128x128, K-split z=2 ----------------
// Per unit: 7 segs x 32 chunks over its K-half. acc folds -sxsw after seg0.
// partial[z] = acc ;  final out = bias - (p0 + p1)
__global__ void __launch_bounds__(256)
gemm_tma_kernel(const __grid_constant__ TmapPack tp, float* __restrict__ part0,
                float* __restrict__ part1) {
    extern __shared__ __align__(1024) char smem[];
    uint32_t sb = smem_u32(smem);
    const int tid = threadIdx.x, lane = tid & 31, warp = tid >> 5;
    const int bn = blockIdx.x, bm = blockIdx.y, bz = blockIdx.z;
    const int wm = (warp >> 2) * 64, wn = (warp & 3) * 32;
    const int kbase = bz * 2048;
    float* part = bz ? part1 : part0;

    if (tid == 0) {
#pragma unroll
        for (int i = 0; i < NSTG; i++) MBAR_INIT(sb + i * 8, 1);
    }
    __syncthreads();

    float acc[4][4][4];
#pragma unroll
    for (int a = 0; a < 4; a++)
#pragma unroll
        for (int b = 0; b < 4; b++)
#pragma unroll
            for (int c = 0; c < 4; c++) acc[a][b][c] = 0.0f;

    const float nss = -__fmul_rn(g_qp[0], g_qp[2]);

    static const int asel[NSEG] = {0, 1, 1, 2, 3, 3, 4};
    static const int bsel[NSEG] = {0, 1, 2, 1, 3, 4, 3};

    if (tid == 0) {
#pragma unroll
        for (int p = 0; p < NSTG; p++) {
            int kx = kbase + p * KCH;   // p < 3 -> seg 0
            uint32_t st = sb + 1024 + p * ST_BYTES;
            MBAR_EXPECT_TX(sb + p * 8, ST_BYTES);
            TMA_2D(st,           &tp.a[0], kx, bm * 128, sb + p * 8);
            TMA_2D(st + A_BYTES, &tp.b[0], kx, bn * 128, sb + p * 8);
        }
    }

    for (int c = 0; c < NCHU; c++) {
        int s = c % NSTG, ph = (c / NSTG) & 1;
        MBAR_WAIT(sb + s * 8, ph);
        uint32_t abase = sb + 1024 + s * ST_BYTES;
        uint32_t bbase = abase + A_BYTES;
#pragma unroll
        for (int kq = 0; kq < 4; kq++) {
            uint32_t af[4][4], bf[4][2];
#pragma unroll
            for (int mt = 0; mt < 4; mt++) {
                int row = wm + mt * 16 + (lane & 15);
                int chk = kq * 2 + (lane >> 4);
                uint32_t off = (uint32_t)(row * 128 + chk * 16);
                uint32_t ad = abase + (off ^ ((off >> 3) & 0x70));
                asm volatile("ldmatrix.sync.aligned.m8n8.x4.shared.b16 {%0,%1,%2,%3},[%4];"
                             : "=r"(af[mt][0]), "=r"(af[mt][1]), "=r"(af[mt][2]), "=r"(af[mt][3])
                             : "r"(ad));
            }
#pragma unroll
            for (int nt = 0; nt < 4; nt++) {
                int row = wn + nt * 8 + (lane & 7);
                int chk = kq * 2 + ((lane >> 3) & 1);
                uint32_t off = (uint32_t)(row * 128 + chk * 16);
                uint32_t bd = bbase + (off ^ ((off >> 3) & 0x70));
                asm volatile("ldmatrix.sync.aligned.m8n8.x2.shared.b16 {%0,%1},[%2];"
                             : "=r"(bf[nt][0]), "=r"(bf[nt][1]) : "r"(bd));
            }
#pragma unroll
            for (int mt = 0; mt < 4; mt++)
#pragma unroll
                for (int nt = 0; nt < 4; nt++) {
                    asm volatile(
                        "mma.sync.aligned.m16n8k16.row.col.f32.bf16.bf16.f32 "
                        "{%0,%1,%2,%3},{%4,%5,%6,%7},{%8,%9},{%0,%1,%2,%3};"
                        : "+f"(acc[mt][nt][0]), "+f"(acc[mt][nt][1]),
                          "+f"(acc[mt][nt][2]), "+f"(acc[mt][nt][3])
                        : "r"(af[mt][0]), "r"(af[mt][1]), "r"(af[mt][2]), "r"(af[mt][3]),
                          "r"(bf[nt][0]), "r"(bf[nt][1]));
                }
        }
        if (c == CHPSU - 1) {   // end of seg0 portion: fold -sx*sw
#pragma unroll
            for (int a = 0; a < 4; a++)
#pragma unroll
                for (int b = 0; b < 4; b++)
#pragma unroll
                    for (int q = 0; q < 4; q++) acc[a][b][q] = __fmul_rn(acc[a][b][q], nss);
        }
        __syncthreads();
        if (tid == 0 && c + NSTG < NCHU) {
            int nc = c + NSTG;
            int seg = nc >> 5, kx = kbase + (nc & 31) * KCH;
            uint32_t st = sb + 1024 + s * ST_BYTES;
            MBAR_EXPECT_TX(sb + s * 8, ST_BYTES);
            TMA_2D(st,           &tp.a[asel[seg]], kx, bm * 128, sb + s * 8);
            TMA_2D(st + A_BYTES, &tp.b[bsel[seg]], kx, bn * 128, sb + s * 8);
        }
    }

    // epilogue: write partial accumulator (no bias yet)
    const int grp = lane >> 2, tig = lane & 3;
#pragma unroll
    for (int mt = 0; mt < 4; mt++)
#pragma unroll
        for (int nt = 0; nt < 4; nt++) {
            int gm = bm * 128 + wm + mt * 16 + grp;
            int gn = bn * 128 + wn + nt * 8 + tig * 2;
            float2 v0, v1;
            v0.x = acc[mt][nt][0]; v0.y = acc[mt][nt][1];
            v1.x = acc[mt][nt][2]; v1.y = acc[mt][nt][3];
            *(float2*)&part[(size_t)gm * OUT_F + gn]       = v0;
            *(float2*)&part[(size_t)(gm + 8) * OUT_F + gn] = v1;
        }
}

// ---------------- reduce: out = bias - (p0 + p1) ----------------
__global__ void reduce_kernel(const float* __restrict__ bias, float* __restrict__ out) {
    size_t i = (size_t)blockIdx.x * blockDim.x + threadIdx.x;   // float4 index
    const size_t N4 = (size_t)BSZ * OUT_F / 4;
    if (i >= N4) return;
    float4 a = ((const float4*)g_p0)[i];
    float4 b = ((const float4*)g_p1)[i];
    int gn = (int)((i * 4) & (OUT_F - 1));
    float4 bj = *(const float4*)&bias[gn];
    float4 o;
    o.x = __fsub_rn(bj.x, __fadd_rn(a.x, b.x));
    o.y = __fsub_rn(bj.y, __fadd_rn(a.y, b.y));
    o.z = __fsub_rn(bj.z, __fadd_rn(a.z, b.z));
    o.w = __fsub_rn(bj.w, __fadd_rn(a.w, b.w));
    ((float4*)out)[i] = o;
}

// ---------------- host: tensormap construction ----------------
typedef CUresult (*EncodeFn)(CUtensorMap*, CUtensorMapDataType, cuuint32_t, void*,
                             const cuuint64_t*, const cuuint64_t*, const cuuint32_t*,
                             const cuuint32_t*, CUtensorMapInterleave, CUtensorMapSwizzle,
                             CUtensorMapL2promotion, CUtensorMapFloatOOBfill);

static void encode_map(EncodeFn enc, CUtensorMap* m, void* ptr, int rows) {
    cuuint64_t dims[2]    = {(cuuint64_t)IN_F, (cuuint64_t)rows};
    cuuint64_t strides[1] = {(cuuint64_t)IN_F * 2};
    cuuint32_t box[2]     = {(cuuint32_t)KCH, 128};
    cuuint32_t estr[2]    = {1, 1};
    enc(m, CU_TENSOR_MAP_DATA_TYPE_BFLOAT16, 2, ptr, dims, strides, box, estr,
        CU_TENSOR_MAP_INTERLEAVE_NONE, CU_TENSOR_MAP_SWIZZLE_128B,
        CU_TENSOR_MAP_L2_PROMOTION_L2_128B, CU_TENSOR_MAP_FLOAT_OOB_FILL_NONE);
}

extern "C" void kernel_launch(void* const* d_in, const int* in_sizes, int n_in,
                              void* d_out, int out_size) {
    const float* x    = (const float*)d_in[0];
    const float* wgt  = (const float*)d_in[1];
    const float* bias = (const float*)d_in[2];
    const float* wn   = (const float*)d_in[3];
    const float* nx   = (const float*)d_in[4];
    const int*   perms= (const int*)  d_in[5];
    const float* mats = (const float*)d_in[6];
    float* out = (float*)d_out;

    make_wmats_kernel<<<(ROUNDS * GROUPS + 255) / 256, 256>>>(mats);
    reset_kernel<<<1, 32>>>();

    prepsplit_x_kernel<<<dim3(BSZ / 32, IN_F / 32), dim3(32, 8)>>>(x, nx);
    prepsplit_w_kernel<<<dim3(OUT_F / 32, IN_F / 32), dim3(32, 8)>>>(wgt, wn);

    // 6 fused passes (2 rounds each); last pass also does min/max
    for (int p = 0; p < ROUNDS / 2; p++) {
        int r = 2 * p;
        round2_kernel<<<dim3(COLS4 / 256, GROUPS), 256>>>(
            p & 1, r,
            perms + (size_t)r * IN_F, perms + (size_t)(r + 1) * IN_F,
            mats + (size_t)r * GROUPS * 4, mats + (size_t)(r + 1) * GROUPS * 4,
            (p == ROUNDS / 2 - 1) ? 1 : 0);
    }

    qparams_kernel<<<1, 32>>>();
    quantT_kernel<<<dim3(COLS / 32, IN_F / 32), dim3(32, 8)>>>();

    void* fp = nullptr;
#if CUDART_VERSION >= 12050
    cudaDriverEntryPointQueryResult qr;
    cudaGetDriverEntryPointByVersion("cuTensorMapEncodeTiled", &fp, 12000,
                                     cudaEnableDefault, &qr);
#else
    cudaGetDriverEntryPoint("cuTensorMapEncodeTiled", &fp, cudaEnableDefault);
#endif
    EncodeFn enc = (EncodeFn)fp;

    void *p_qx, *p_xhi, *p_xlo, *p_nxhi, *p_nxlo, *p_qw, *p_wnhi, *p_wnlo, *p_wphi, *p_wplo;
    void *p_p0, *p_p1;
    cudaGetSymbolAddress(&p_qx, g_qx);     cudaGetSymbolAddress(&p_xhi, g_xhi);
    cudaGetSymbolAddress(&p_xlo, g_xlo);   cudaGetSymbolAddress(&p_nxhi, g_nxhi);
    cudaGetSymbolAddress(&p_nxlo, g_nxlo); cudaGetSymbolAddress(&p_qw, g_qw);
    cudaGetSymbolAddress(&p_wnhi, g_wnhi); cudaGetSymbolAddress(&p_wnlo, g_wnlo);
    cudaGetSymbolAddress(&p_wphi, g_wphi); cudaGetSymbolAddress(&p_wplo, g_wplo);
    cudaGetSymbolAddress(&p_p0, g_p0);     cudaGetSymbolAddress(&p_p1, g_p1);

    TmapPack tp;
    encode_map(enc, &tp.a[0], p_qx,   BSZ);
    encode_map(enc, &tp.a[1], p_xhi,  BSZ);
    encode_map(enc, &tp.a[2], p_xlo,  BSZ);
    encode_map(enc, &tp.a[3], p_nxhi, BSZ);
    encode_map(enc, &tp.a[4], p_nxlo, BSZ);
    encode_map(enc, &tp.b[0], p_qw,   OUT_F);
    encode_map(enc, &tp.b[1], p_wnhi, OUT_F);
    encode_map(enc, &tp.b[2], p_wnlo, OUT_F);
    encode_map(enc, &tp.b[3], p_wphi, OUT_F);
    encode_map(enc, &tp.b[4], p_wplo, OUT_F);

    cudaFuncSetAttribute(gemm_tma_kernel, cudaFuncAttributeMaxDynamicSharedMemorySize, DSMEM);
    gemm_tma_kernel<<<dim3(OUT_F / 128, BSZ / 128, 2), 256, DSMEM>>>(
        tp, (float*)p_p0, (float*)p_p1);
    reduce_kernel<<<(BSZ * OUT_F / 4 + 255) / 256, 256>>>(bias, out);
}

// round 16
// speedup vs baseline: 3.0925x; 1.0008x over previous
#include <cuda_runtime.h>
#include <cuda.h>
#include <cuda_bf16.h>
#include <math.h>
#include <stdint.h>

#define IN_F   4096
#define OUT_F  1024
#define BSZ    8192
#define COLS   9216
#define COLS4  2304
#define GROUPS 2048
#define ROUNDS 12

#define KCH    64
#define NSEG   7
#define NZ     4               // K-split factor
#define CHPSU  16              // chunks per segment per K-quarter
#define NCHU   (NSEG * CHPSU)  // 112 chunks per unit
#define NSTG   3
#define A_BYTES 16384          // 128 x 64 bf16
#define B_BYTES 16384
#define ST_BYTES (A_BYTES + B_BYTES)
#define DSMEM (1024 + NSTG * ST_BYTES)   // 99328 -> 2 CTAs/SM

// ---------------- device scratch ----------------
__device__ __align__(128) float g_a[(size_t)IN_F * COLS];
__device__ __align__(128) float g_b[(size_t)IN_F * COLS];
__device__ __align__(128) float g_wmats[ROUNDS * GROUPS * 4];
__device__ unsigned g_mm[4];
__device__ float    g_qp[4];
__device__ __align__(128) float g_part[NZ][(size_t)BSZ * OUT_F];   // K-split partials

__device__ __align__(128) __nv_bfloat16 g_qx  [(size_t)BSZ   * IN_F];
__device__ __align__(128) __nv_bfloat16 g_qw  [(size_t)OUT_F * IN_F];
__device__ __align__(128) __nv_bfloat16 g_xhi [(size_t)BSZ   * IN_F];
__device__ __align__(128) __nv_bfloat16 g_xlo [(size_t)BSZ   * IN_F];
__device__ __align__(128) __nv_bfloat16 g_nxhi[(size_t)BSZ   * IN_F];
__device__ __align__(128) __nv_bfloat16 g_nxlo[(size_t)BSZ   * IN_F];
__device__ __align__(128) __nv_bfloat16 g_wnhi[(size_t)OUT_F * IN_F];
__device__ __align__(128) __nv_bfloat16 g_wnlo[(size_t)OUT_F * IN_F];
__device__ __align__(128) __nv_bfloat16 g_wphi[(size_t)OUT_F * IN_F];
__device__ __align__(128) __nv_bfloat16 g_wplo[(size_t)OUT_F * IN_F];

struct TmapPack { CUtensorMap a[5]; CUtensorMap b[5]; };

// ---------------- helpers ----------------
__device__ __forceinline__ unsigned enc_f(float f) {
    unsigned u = __float_as_uint(f);
    return (u & 0x80000000u) ? ~u : (u | 0x80000000u);
}
__device__ __forceinline__ float dec_f(unsigned k) {
    return __uint_as_float((k & 0x80000000u) ? (k ^ 0x80000000u) : ~k);
}
__device__ __forceinline__ uint32_t smem_u32(const void* p) {
    uint32_t a;
    asm("{ .reg .u64 t; cvta.to.shared.u64 t, %1; cvt.u32.u64 %0, t; }" : "=r"(a) : "l"(p));
    return a;
}
__device__ __forceinline__ void split1(float v, __nv_bfloat16& h, __nv_bfloat16& l) {
    h = __float2bfloat16_rn(v);
    l = __float2bfloat16_rn(__fsub_rn(v, __bfloat162float(h)));
}

#define MBAR_INIT(addr, cnt) \
    asm volatile("mbarrier.init.shared.b64 [%0], %1;" :: "r"(addr), "r"(cnt) : "memory")
#define MBAR_EXPECT_TX(addr, bytes) \
    asm volatile("mbarrier.arrive.expect_tx.shared.b64 _, [%0], %1;" :: "r"(addr), "r"(bytes) : "memory")
#define MBAR_WAIT(addr, par) do {                                              \
    asm volatile(                                                              \
        "{\n\t.reg .pred P;\n\t"                                               \
        "WL_%=:\n\t"                                                           \
        "mbarrier.try_wait.parity.acquire.cta.shared::cta.b64 P, [%0], %1, 0x989680;\n\t" \
        "@P bra.uni WD_%=;\n\t"                                                \
        "bra.uni WL_%=;\n\t"                                                   \
        "WD_%=:\n\t}"                                                          \
        :: "r"(addr), "r"(par) : "memory");                                    \
} while (0)

#define TMA_2D(smem, map, cx, cy, mbar) \
    asm volatile("cp.async.bulk.tensor.2d.shared::cta.global.tile.mbarrier::complete_tx::bytes " \
                 "[%0], [%1, {%2, %3}], [%4];" \
                 :: "r"(smem), "l"(map), "r"(cx), "r"(cy), "r"(mbar) : "memory")

// ---------------- inv(m)^T via LU w/ partial pivoting ----------------
__global__ void make_wmats_kernel(const float* __restrict__ mats) {
    int idx = blockIdx.x * blockDim.x + threadIdx.x;
    if (idx >= ROUNDS * GROUPS) return;
    const float* m = mats + (size_t)idx * 4;
    float a = m[0], b = m[1], c = m[2], d = m[3];
    float i00, i01, i10, i11;
    if (fabsf(c) > fabsf(a)) {
        float l   = __fdiv_rn(a, c);
        float u22 = __fmaf_rn(-l, d, b);
        float x2c1 = __fdiv_rn(1.0f, u22);
        float x1c1 = __fdiv_rn(__fmul_rn(-d, x2c1), c);
        float x2c2 = __fdiv_rn(-l, u22);
        float x1c2 = __fdiv_rn(__fmaf_rn(-d, x2c2, 1.0f), c);
        i00 = x1c1; i01 = x1c2; i10 = x2c1; i11 = x2c2;
    } else {
        float l   = __fdiv_rn(c, a);
        float u22 = __fmaf_rn(-l, b, d);
        float x2c1 = __fdiv_rn(-l, u22);
        float x1c1 = __fdiv_rn(__fmaf_rn(-b, x2c1, 1.0f), a);
        float x2c2 = __fdiv_rn(1.0f, u22);
        float x1c2 = __fdiv_rn(__fmul_rn(-b, x2c2), a);
        i00 = x1c1; i01 = x1c2; i10 = x2c1; i11 = x2c2;
    }
    float* o = g_wmats + (size_t)idx * 4;
    o[0] = i00; o[1] = i10; o[2] = i01; o[3] = i11;
}

// ---------------- fused transpose+add + bf16 splits ----------------
__global__ void prepsplit_x_kernel(const float* __restrict__ x, const float* __restrict__ nx) {
    __shared__ float tile[32][33];
    int c0 = blockIdx.x * 32, k0 = blockIdx.y * 32;
    int tx = threadIdx.x, ty = threadIdx.y;
#pragma unroll
    for (int i = ty; i < 32; i += 8) {
        size_t idx = (size_t)(c0 + i) * IN_F + k0 + tx;
        float vx = x[idx], vn = nx[idx];
        tile[i][tx] = __fadd_rn(vx, vn);
        __nv_bfloat16 h, l;
        split1(vx, h, l); g_xhi[idx]  = h; g_xlo[idx]  = l;
        split1(vn, h, l); g_nxhi[idx] = h; g_nxlo[idx] = l;
    }
    __syncthreads();
#pragma unroll
    for (int i = ty; i < 32; i += 8)
        g_a[(size_t)(k0 + i) * COLS + c0 + tx] = tile[tx][i];
}
__global__ void prepsplit_w_kernel(const float* __restrict__ w, const float* __restrict__ wn) {
    __shared__ float tile[32][33];
    int c0 = blockIdx.x * 32, k0 = blockIdx.y * 32;
    int tx = threadIdx.x, ty = threadIdx.y;
#pragma unroll
    for (int i = ty; i < 32; i += 8) {
        size_t idx = (size_t)(c0 + i) * IN_F + k0 + tx;
        float vw = w[idx], vn = wn[idx];
        float vp = __fadd_rn(vw, vn);
        tile[i][tx] = vp;
        __nv_bfloat16 h, l;
        split1(vn, h, l); g_wnhi[idx] = h; g_wnlo[idx] = l;
        split1(vp, h, l); g_wphi[idx] = h; g_wplo[idx] = l;
    }
    __syncthreads();
#pragma unroll
    for (int i = ty; i < 32; i += 8)
        g_a[(size_t)(k0 + i) * COLS + BSZ + c0 + tx] = tile[tx][i];
}

// ---------------- TWO fused permutation + 2x2-mix rounds (bitwise-exact, NO FMA) ----
__global__ void round2_kernel(int dir, int r,
                              const int* __restrict__ perm0,
                              const int* __restrict__ perm1,
                              const float* __restrict__ matsx0,
                              const float* __restrict__ matsx1,
                              int do_mm) {
    const float* in  = dir ? g_b : g_a;
    float*       out = dir ? g_a : g_b;
    int g   = blockIdx.y;
    int col = blockIdx.x * 256 + threadIdx.x;
    int i0 = __ldg(&perm1[2 * g]);
    int i1 = __ldg(&perm1[2 * g + 1]);
    int g0 = i0 >> 1, p0 = i0 & 1;
    int g1 = i1 >> 1, p1 = i1 & 1;
    int ra0 = __ldg(&perm0[2 * g0]), rb0 = __ldg(&perm0[2 * g0 + 1]);
    int ra1 = __ldg(&perm0[2 * g1]), rb1 = __ldg(&perm0[2 * g1 + 1]);
    bool isx = (col < BSZ / 4);
    const float* m0base = isx ? matsx0 : (g_wmats + (size_t)r * GROUPS * 4);
    const float* m1base = isx ? matsx1 : (g_wmats + (size_t)(r + 1) * GROUPS * 4);
    float4 mA = __ldg((const float4*)(m0base + (size_t)g0 * 4));
    float4 mB = __ldg((const float4*)(m0base + (size_t)g1 * 4));
    float4 mC = __ldg((const float4*)(m1base + (size_t)g * 4));
    float c00 = p0 ? mA.z : mA.x, c01 = p0 ? mA.w : mA.y;
    float c10 = p1 ? mB.z : mB.x, c11 = p1 ? mB.w : mB.y;
    float4 a0 = ((const float4*)(in + (size_t)ra0 * COLS))[col];
    float4 b0 = ((const float4*)(in + (size_t)rb0 * COLS))[col];
    float4 a1 = ((const float4*)(in + (size_t)ra1 * COLS))[col];
    float4 b1 = ((const float4*)(in + (size_t)rb1 * COLS))[col];
    float4 v0, v1, o0, o1;
    v0.x = __fadd_rn(__fmul_rn(c00, a0.x), __fmul_rn(c01, b0.x));
    v0.y = __fadd_rn(__fmul_rn(c00, a0.y), __fmul_rn(c01, b0.y));
    v0.z = __fadd_rn(__fmul_rn(c00, a0.z), __fmul_rn(c01, b0.z));
    v0.w = __fadd_rn(__fmul_rn(c00, a0.w), __fmul_rn(c01, b0.w));
    v1.x = __fadd_rn(__fmul_rn(c10, a1.x), __fmul_rn(c11, b1.x));
    v1.y = __fadd_rn(__fmul_rn(c10, a1.y), __fmul_rn(c11, b1.y));
    v1.z = __fadd_rn(__fmul_rn(c10, a1.z), __fmul_rn(c11, b1.z));
    v1.w = __fadd_rn(__fmul_rn(c10, a1.w), __fmul_rn(c11, b1.w));
    o0.x = __fadd_rn(__fmul_rn(mC.x, v0.x), __fmul_rn(mC.y, v1.x));
    o0.y = __fadd_rn(__fmul_rn(mC.x, v0.y), __fmul_rn(mC.y, v1.y));
    o0.z = __fadd_rn(__fmul_rn(mC.x, v0.z), __fmul_rn(mC.y, v1.z));
    o0.w = __fadd_rn(__fmul_rn(mC.x, v0.w), __fmul_rn(mC.y, v1.w));
    o1.x = __fadd_rn(__fmul_rn(mC.z, v0.x), __fmul_rn(mC.w, v1.x));
    o1.y = __fadd_rn(__fmul_rn(mC.z, v0.y), __fmul_rn(mC.w, v1.y));
    o1.z = __fadd_rn(__fmul_rn(mC.z, v0.z), __fmul_rn(mC.w, v1.z));
    o1.w = __fadd_rn(__fmul_rn(mC.z, v0.w), __fmul_rn(mC.w, v1.w));
    ((float4*)(out + (size_t)(2 * g)     * COLS))[col] = o0;
    ((float4*)(out + (size_t)(2 * g + 1) * COLS))[col] = o1;

    if (do_mm) {
        float lo = fminf(fminf(fminf(o0.x, o0.y), fminf(o0.z, o0.w)),
                         fminf(fminf(o1.x, o1.y), fminf(o1.z, o1.w)));
        float hi = fmaxf(fmaxf(fmaxf(o0.x, o0.y), fmaxf(o0.z, o0.w)),
                         fmaxf(fmaxf(o1.x, o1.y), fmaxf(o1.z, o1.w)));
        __shared__ float red[256];
        red[threadIdx.x] = lo; __syncthreads();
        for (int s = 128; s > 0; s >>= 1) {
            if (threadIdx.x < s) red[threadIdx.x] = fminf(red[threadIdx.x], red[threadIdx.x + s]);
            __syncthreads();
        }
        if (threadIdx.x == 0) atomicMin(&g_mm[isx ? 0 : 2], enc_f(red[0]));
        __syncthreads();
        red[threadIdx.x] = hi; __syncthreads();
        for (int s = 128; s > 0; s >>= 1) {
            if (threadIdx.x < s) red[threadIdx.x] = fmaxf(red[threadIdx.x], red[threadIdx.x + s]);
            __syncthreads();
        }
        if (threadIdx.x == 0) atomicMax(&g_mm[isx ? 1 : 3], enc_f(red[0]));
    }
}

// ---------------- reset + qparams ----------------
__global__ void reset_kernel() {
    if (threadIdx.x == 0) {
        g_mm[0] = 0xFFFFFFFFu; g_mm[1] = 0u;
        g_mm[2] = 0xFFFFFFFFu; g_mm[3] = 0u;
    }
}
__global__ void qparams_kernel() {
    if (threadIdx.x == 0) {
        float lx = dec_f(g_mm[0]), hx = dec_f(g_mm[1]);
        float sx = __fdiv_rn(__fsub_rn(hx, lx), 255.0f);
        float zx = rintf(__fsub_rn(-128.0f, __fdiv_rn(lx, sx)));
        float lw = dec_f(g_mm[2]), hw = dec_f(g_mm[3]);
        float sw = __fdiv_rn(__fsub_rn(hw, lw), 255.0f);
        float zw = rintf(__fsub_rn(-128.0f, __fdiv_rn(lw, sw)));
        g_qp[0] = sx; g_qp[1] = zx; g_qp[2] = sw; g_qp[3] = zw;
    }
}

// ---------------- quantize -> integer (q - zp) bf16, K-major ----------------
__global__ void quantT_kernel() {
    __shared__ float tile[32][33];
    int c0 = blockIdx.x * 32, k0 = blockIdx.y * 32;
    int tx = threadIdx.x, ty = threadIdx.y;
    bool isx = (c0 < BSZ);
    float s = isx ? g_qp[0] : g_qp[2];
    float z = isx ? g_qp[1] : g_qp[3];
#pragma unroll
    for (int i = ty; i < 32; i += 8) {
        float t = g_a[(size_t)(k0 + i) * COLS + c0 + tx];
        float q = rintf(__fadd_rn(__fdiv_rn(t, s), z));
        q = fminf(fmaxf(q, -128.0f), 127.0f);
        tile[i][tx] = __fsub_rn(q, z);
    }
    __syncthreads();
    __nv_bfloat16* dst = isx ? g_qx : g_qw;
    int cb = isx ? c0 : (c0 - BSZ);
#pragma unroll
    for (int i = ty; i < 32; i += 8) {
        dst[(size_t)(cb + i) * IN_F + k0 + tx] = __float2bfloat16_rn(tile[tx][i]);
    }
}

// ---------------- TMA-fed mma.sync GEMM, tile 128x128, K-split z=4 ----------------
// Per unit: 7 segs x 16 chunks over its K-quarter. acc folds -sxsw after seg0.
// partial[z] = acc ;  final out = bias - sum_z p[z]
__global__ void __launch_bounds__(256)
gemm_tma_kernel(const __grid_constant__ TmapPack tp) {
    extern __shared__ __align__(1024) char smem[];
    uint32_t sb = smem_u32(smem);
    const int tid = threadIdx.x, lane = tid & 31, warp = tid >> 5;
    const int bn = blockIdx.x, bm = blockIdx.y, bz = blockIdx.z;
    const int wm = (warp >> 2) * 64, wn = (warp & 3) * 32;
    const int kbase = bz * (IN_F / NZ);
    float* part = g_part[bz];

    if (tid == 0) {
#pragma unroll
        for (int i = 0; i < NSTG; i++) MBAR_INIT(sb + i * 8, 1);
    }
    __syncthreads();

    float acc[4][4][4];
#pragma unroll
    for (int a = 0; a < 4; a++)
#pragma unroll
        for (int b = 0; b < 4; b++)
#pragma unroll
            for (int c = 0; c < 4; c++) acc[a][b][c] = 0.0f;

    const float nss = -__fmul_rn(g_qp[0], g_qp[2]);

    static const int asel[NSEG] = {0, 1, 1, 2, 3, 3, 4};
    static const int bsel[NSEG] = {0, 1, 2, 1, 3, 4, 3};

    if (tid == 0) {
#pragma unroll
        for (int p = 0; p < NSTG; p++) {
            int kx = kbase + p * KCH;   // p < 3 -> seg 0
            uint32_t st = sb + 1024 + p * ST_BYTES;
            MBAR_EXPECT_TX(sb + p * 8, ST_BYTES);
            TMA_2D(st,           &tp.a[0], kx, bm * 128, sb + p * 8);
            TMA_2D(st + A_BYTES, &tp.b[0], kx, bn * 128, sb + p * 8);
        }
    }

    for (int c = 0; c < NCHU; c++) {
        int s = c % NSTG, ph = (c / NSTG) & 1;
        MBAR_WAIT(sb + s * 8, ph);
        uint32_t abase = sb + 1024 + s * ST_BYTES;
        uint32_t bbase = abase + A_BYTES;
#pragma unroll
        for (int kq = 0; kq < 4; kq++) {
            uint32_t af[4][4], bf[4][2];
#pragma unroll
            for (int mt = 0; mt < 4; mt++) {
                int row = wm + mt * 16 + (lane & 15);
                int chk = kq * 2 + (lane >> 4);
                uint32_t off = (uint32_t)(row * 128 + chk * 16);
                uint32_t ad = abase + (off ^ ((off >> 3) & 0x70));
                asm volatile("ldmatrix.sync.aligned.m8n8.x4.shared.b16 {%0,%1,%2,%3},[%4];"
                             : "=r"(af[mt][0]), "=r"(af[mt][1]), "=r"(af[mt][2]), "=r"(af[mt][3])
                             : "r"(ad));
            }
#pragma unroll
            for (int nt = 0; nt < 4; nt++) {
                int row = wn + nt * 8 + (lane & 7);
                int chk = kq * 2 + ((lane >> 3) & 1);
                uint32_t off = (uint32_t)(row * 128 + chk * 16);
                uint32_t bd = bbase + (off ^ ((off >> 3) & 0x70));
                asm volatile("ldmatrix.sync.aligned.m8n8.x2.shared.b16 {%0,%1},[%2];"
                             : "=r"(bf[nt][0]), "=r"(bf[nt][1]) : "r"(bd));
            }
#pragma unroll
            for (int mt = 0; mt < 4; mt++)
#pragma unroll
                for (int nt = 0; nt < 4; nt++) {
                    asm volatile(
                        "mma.sync.aligned.m16n8k16.row.col.f32.bf16.bf16.f32 "
                        "{%0,%1,%2,%3},{%4,%5,%6,%7},{%8,%9},{%0,%1,%2,%3};"
                        : "+f"(acc[mt][nt][0]), "+f"(acc[mt][nt][1]),
                          "+f"(acc[mt][nt][2]), "+f"(acc[mt][nt][3])
                        : "r"(af[mt][0]), "r"(af[mt][1]), "r"(af[mt][2]), "r"(af[mt][3]),
                          "r"(bf[nt][0]), "r"(bf[nt][1]));
                }
        }
        if (c == CHPSU - 1) {   // end of seg0 portion: fold -sx*sw (exact per K-slice)
#pragma unroll
            for (int a = 0; a < 4; a++)
#pragma unroll
                for (int b = 0; b < 4; b++)
#pragma unroll
                    for (int q = 0; q < 4; q++) acc[a][b][q] = __fmul_rn(acc[a][b][q], nss);
        }
        __syncthreads();
        if (tid == 0 && c + NSTG < NCHU) {
            int nc = c + NSTG;
            int seg = nc / CHPSU, kx = kbase + (nc % CHPSU) * KCH;
            uint32_t st = sb + 1024 + s * ST_BYTES;
            MBAR_EXPECT_TX(sb + s * 8, ST_BYTES);
            TMA_2D(st,           &tp.a[asel[seg]], kx, bm * 128, sb + s * 8);
            TMA_2D(st + A_BYTES, &tp.b[bsel[seg]], kx, bn * 128, sb + s * 8);
        }
    }

    // epilogue: write partial accumulator (no bias yet)
    const int grp = lane >> 2, tig = lane & 3;
#pragma unroll
    for (int mt = 0; mt < 4; mt++)
#pragma unroll
        for (int nt = 0; nt < 4; nt++) {
            int gm = bm * 128 + wm + mt * 16 + grp;
            int gn = bn * 128 + wn + nt * 8 + tig * 2;
            float2 v0, v1;
            v0.x = acc[mt][nt][0]; v0.y = acc[mt][nt][1];
            v1.x = acc[mt][nt][2]; v1.y = acc[mt][nt][3];
            *(float2*)&part[(size_t)gm * OUT_F + gn]       = v0;
            *(float2*)&part[(size_t)(gm + 8) * OUT_F + gn] = v1;
        }
}

// ---------------- reduce: out = bias - (p0 + p1 + p2 + p3) ----------------
__global__ void reduce_kernel(const float* __restrict__ bias, float* __restrict__ out) {
    size_t i = (size_t)blockIdx.x * blockDim.x + threadIdx.x;   // float4 index
    const size_t N4 = (size_t)BSZ * OUT_F / 4;
    if (i >= N4) return;
    float4 a = ((const float4*)g_part[0])[i];
    float4 b = ((const float4*)g_part[1])[i];
    float4 c = ((const float4*)g_part[2])[i];
    float4 d = ((const float4*)g_part[3])[i];
    int gn = (int)((i * 4) & (OUT_F - 1));
    float4 bj = *(const float4*)&bias[gn];
    float4 o;
    o.x = __fsub_rn(bj.x, __fadd_rn(__fadd_rn(a.x, b.x), __fadd_rn(c.x, d.x)));
    o.y = __fsub_rn(bj.y, __fadd_rn(__fadd_rn(a.y, b.y), __fadd_rn(c.y, d.y)));
    o.z = __fsub_rn(bj.z, __fadd_rn(__fadd_rn(a.z, b.z), __fadd_rn(c.z, d.z)));
    o.w = __fsub_rn(bj.w, __fadd_rn(__fadd_rn(a.w, b.w), __fadd_rn(c.w, d.w)));
    ((float4*)out)[i] = o;
}

// ---------------- host: tensormap construction ----------------
typedef CUresult (*EncodeFn)(CUtensorMap*, CUtensorMapDataType, cuuint32_t, void*,
                             const cuuint64_t*, const cuuint64_t*, const cuuint32_t*,
                             const cuuint32_t*, CUtensorMapInterleave, CUtensorMapSwizzle,
                             CUtensorMapL2promotion, CUtensorMapFloatOOBfill);

static void encode_map(EncodeFn enc, CUtensorMap* m, void* ptr, int rows) {
    cuuint64_t dims[2]    = {(cuuint64_t)IN_F, (cuuint64_t)rows};
    cuuint64_t strides[1] = {(cuuint64_t)IN_F * 2};
    cuuint32_t box[2]     = {(cuuint32_t)KCH, 128};
    cuuint32_t estr[2]    = {1, 1};
    enc(m, CU_TENSOR_MAP_DATA_TYPE_BFLOAT16, 2, ptr, dims, strides, box, estr,
        CU_TENSOR_MAP_INTERLEAVE_NONE, CU_TENSOR_MAP_SWIZZLE_128B,
        CU_TENSOR_MAP_L2_PROMOTION_L2_128B, CU_TENSOR_MAP_FLOAT_OOB_FILL_NONE);
}

extern "C" void kernel_launch(void* const* d_in, const int* in_sizes, int n_in,
                              void* d_out, int out_size) {
    const float* x    = (const float*)d_in[0];
    const float* wgt  = (const float*)d_in[1];
    const float* bias = (const float*)d_in[2];
    const float* wn   = (const float*)d_in[3];
    const float* nx   = (const float*)d_in[4];
    const int*   perms= (const int*)  d_in[5];
    const float* mats = (const float*)d_in[6];
    float* out = (float*)d_out;

    make_wmats_kernel<<<(ROUNDS * GROUPS + 255) / 256, 256>>>(mats);
    reset_kernel<<<1, 32>>>();

    prepsplit_x_kernel<<<dim3(BSZ / 32, IN_F / 32), dim3(32, 8)>>>(x, nx);
    prepsplit_w_kernel<<<dim3(OUT_F / 32, IN_F / 32), dim3(32, 8)>>>(wgt, wn);

    // 6 fused passes (2 rounds each); last pass also does min/max
    for (int p = 0; p < ROUNDS / 2; p++) {
        int r = 2 * p;
        round2_kernel<<<dim3(COLS4 / 256, GROUPS), 256>>>(
            p & 1, r,
            perms + (size_t)r * IN_F, perms + (size_t)(r + 1) * IN_F,
            mats + (size_t)r * GROUPS * 4, mats + (size_t)(r + 1) * GROUPS * 4,
            (p == ROUNDS / 2 - 1) ? 1 : 0);
    }

    qparams_kernel<<<1, 32>>>();
    quantT_kernel<<<dim3(COLS / 32, IN_F / 32), dim3(32, 8)>>>();

    void* fp = nullptr;
#if CUDART_VERSION >= 12050
    cudaDriverEntryPointQueryResult qr;
    cudaGetDriverEntryPointByVersion("cuTensorMapEncodeTiled", &fp, 12000,
                                     cudaEnableDefault, &qr);
#else
    cudaGetDriverEntryPoint("cuTensorMapEncodeTiled", &fp, cudaEnableDefault);
#endif
    EncodeFn enc = (EncodeFn)fp;

    void *p_qx, *p_xhi, *p_xlo, *p_nxhi, *p_nxlo, *p_qw, *p_wnhi, *p_wnlo, *p_wphi, *p_wplo;
    cudaGetSymbolAddress(&p_qx, g_qx);     cudaGetSymbolAddress(&p_xhi, g_xhi);
    cudaGetSymbolAddress(&p_xlo, g_xlo);   cudaGetSymbolAddress(&p_nxhi, g_nxhi);
    cudaGetSymbolAddress(&p_nxlo, g_nxlo); cudaGetSymbolAddress(&p_qw, g_qw);
    cudaGetSymbolAddress(&p_wnhi, g_wnhi); cudaGetSymbolAddress(&p_wnlo, g_wnlo);
    cudaGetSymbolAddress(&p_wphi, g_wphi); cudaGetSymbolAddress(&p_wplo, g_wplo);

    TmapPack tp;
    encode_map(enc, &tp.a[0], p_qx,   BSZ);
    encode_map(enc, &tp.a[1], p_xhi,  BSZ);
    encode_map(enc, &tp.a[2], p_xlo,  BSZ);
    encode_map(enc, &tp.a[3], p_nxhi, BSZ);
    encode_map(enc, &tp.a[4], p_nxlo, BSZ);
    encode_map(enc, &tp.b[0], p_qw,   OUT_F);
    encode_map(enc, &tp.b[1], p_wnhi, OUT_F);
    encode_map(enc, &tp.b[2], p_wnlo, OUT_F);
    encode_map(enc, &tp.b[3], p_wphi, OUT_F);
    encode_map(enc, &tp.b[4], p_wplo, OUT_F);

    cudaFuncSetAttribute(gemm_tma_kernel, cudaFuncAttributeMaxDynamicSharedMemorySize, DSMEM);
    gemm_tma_kernel<<<dim3(OUT_F / 128, BSZ / 128, NZ), 256, DSMEM>>>(tp);
    reduce_kernel<<<(BSZ * OUT_F / 4 + 255) / 256, 256>>>(bias, out);
}

// round 17
// speedup vs baseline: 3.1826x; 1.0291x over previous
#include <cuda_runtime.h>
#include <cuda.h>
#include <cuda_bf16.h>
#include <math.h>
#include <stdint.h>

#define IN_F   4096
#define OUT_F  1024
#define BSZ    8192
#define COLS   9216
#define COLS4  2304
#define GROUPS 2048
#define ROUNDS 12

#define KCH    64
#define NZ     4               // K-split for correction GEMM
#define CHPSU  16              // chunks per segment per K-quarter
#define NSEGC  6
#define NCHC   (NSEGC * CHPSU) // 96 chunks per corr unit
#define NCHQ   64              // seg0: full K, 64 chunks
#define NSTG   3
#define A_BYTES 16384          // 128 x 64 bf16
#define B_BYTES 16384
#define ST_BYTES (A_BYTES + B_BYTES)
#define DSMEM (1024 + NSTG * ST_BYTES)   // 99328 -> 2 CTAs/SM

// ---------------- device scratch ----------------
__device__ __align__(128) float g_a[(size_t)IN_F * COLS];
__device__ __align__(128) float g_b[(size_t)IN_F * COLS];
__device__ __align__(128) float g_wmats[ROUNDS * GROUPS * 4];
__device__ unsigned g_mm[4];
__device__ float    g_qp[4];
__device__ __align__(128) float g_part[NZ][(size_t)BSZ * OUT_F];   // corr partials
__device__ __align__(128) float g_qpart[(size_t)BSZ * OUT_F];      // sxsw * Sum_q

__device__ __align__(128) __nv_bfloat16 g_qx  [(size_t)BSZ   * IN_F];
__device__ __align__(128) __nv_bfloat16 g_qw  [(size_t)OUT_F * IN_F];
__device__ __align__(128) __nv_bfloat16 g_xhi [(size_t)BSZ   * IN_F];
__device__ __align__(128) __nv_bfloat16 g_xlo [(size_t)BSZ   * IN_F];
__device__ __align__(128) __nv_bfloat16 g_nxhi[(size_t)BSZ   * IN_F];
__device__ __align__(128) __nv_bfloat16 g_nxlo[(size_t)BSZ   * IN_F];
__device__ __align__(128) __nv_bfloat16 g_wnhi[(size_t)OUT_F * IN_F];
__device__ __align__(128) __nv_bfloat16 g_wnlo[(size_t)OUT_F * IN_F];
__device__ __align__(128) __nv_bfloat16 g_wphi[(size_t)OUT_F * IN_F];
__device__ __align__(128) __nv_bfloat16 g_wplo[(size_t)OUT_F * IN_F];

struct TmapPack { CUtensorMap a[5]; CUtensorMap b[5]; };

// ---------------- helpers ----------------
__device__ __forceinline__ unsigned enc_f(float f) {
    unsigned u = __float_as_uint(f);
    return (u & 0x80000000u) ? ~u : (u | 0x80000000u);
}
__device__ __forceinline__ float dec_f(unsigned k) {
    return __uint_as_float((k & 0x80000000u) ? (k ^ 0x80000000u) : ~k);
}
__device__ __forceinline__ uint32_t smem_u32(const void* p) {
    uint32_t a;
    asm("{ .reg .u64 t; cvta.to.shared.u64 t, %1; cvt.u32.u64 %0, t; }" : "=r"(a) : "l"(p));
    return a;
}
__device__ __forceinline__ void split1(float v, __nv_bfloat16& h, __nv_bfloat16& l) {
    h = __float2bfloat16_rn(v);
    l = __float2bfloat16_rn(__fsub_rn(v, __bfloat162float(h)));
}

#define MBAR_INIT(addr, cnt) \
    asm volatile("mbarrier.init.shared.b64 [%0], %1;" :: "r"(addr), "r"(cnt) : "memory")
#define MBAR_EXPECT_TX(addr, bytes) \
    asm volatile("mbarrier.arrive.expect_tx.shared.b64 _, [%0], %1;" :: "r"(addr), "r"(bytes) : "memory")
#define MBAR_WAIT(addr, par) do {                                              \
    asm volatile(                                                              \
        "{\n\t.reg .pred P;\n\t"                                               \
        "WL_%=:\n\t"                                                           \
        "mbarrier.try_wait.parity.acquire.cta.shared::cta.b64 P, [%0], %1, 0x989680;\n\t" \
        "@P bra.uni WD_%=;\n\t"                                                \
        "bra.uni WL_%=;\n\t"                                                   \
        "WD_%=:\n\t}"                                                          \
        :: "r"(addr), "r"(par) : "memory");                                    \
} while (0)

#define TMA_2D(smem, map, cx, cy, mbar) \
    asm volatile("cp.async.bulk.tensor.2d.shared::cta.global.tile.mbarrier::complete_tx::bytes " \
                 "[%0], [%1, {%2, %3}], [%4];" \
                 :: "r"(smem), "l"(map), "r"(cx), "r"(cy), "r"(mbar) : "memory")

// ---------------- inv(m)^T via LU w/ partial pivoting ----------------
__global__ void make_wmats_kernel(const float* __restrict__ mats) {
    int idx = blockIdx.x * blockDim.x + threadIdx.x;
    if (idx >= ROUNDS * GROUPS) return;
    const float* m = mats + (size_t)idx * 4;
    float a = m[0], b = m[1], c = m[2], d = m[3];
    float i00, i01, i10, i11;
    if (fabsf(c) > fabsf(a)) {
        float l   = __fdiv_rn(a, c);
        float u22 = __fmaf_rn(-l, d, b);
        float x2c1 = __fdiv_rn(1.0f, u22);
        float x1c1 = __fdiv_rn(__fmul_rn(-d, x2c1), c);
        float x2c2 = __fdiv_rn(-l, u22);
        float x1c2 = __fdiv_rn(__fmaf_rn(-d, x2c2, 1.0f), c);
        i00 = x1c1; i01 = x1c2; i10 = x2c1; i11 = x2c2;
    } else {
        float l   = __fdiv_rn(c, a);
        float u22 = __fmaf_rn(-l, b, d);
        float x2c1 = __fdiv_rn(-l, u22);
        float x1c1 = __fdiv_rn(__fmaf_rn(-b, x2c1, 1.0f), a);
        float x2c2 = __fdiv_rn(1.0f, u22);
        float x1c2 = __fdiv_rn(__fmul_rn(-b, x2c2), a);
        i00 = x1c1; i01 = x1c2; i10 = x2c1; i11 = x2c2;
    }
    float* o = g_wmats + (size_t)idx * 4;
    o[0] = i00; o[1] = i10; o[2] = i01; o[3] = i11;
}

// ---------------- fused transpose+add + bf16 splits ----------------
__global__ void prepsplit_x_kernel(const float* __restrict__ x, const float* __restrict__ nx) {
    __shared__ float tile[32][33];
    int c0 = blockIdx.x * 32, k0 = blockIdx.y * 32;
    int tx = threadIdx.x, ty = threadIdx.y;
#pragma unroll
    for (int i = ty; i < 32; i += 8) {
        size_t idx = (size_t)(c0 + i) * IN_F + k0 + tx;
        float vx = x[idx], vn = nx[idx];
        tile[i][tx] = __fadd_rn(vx, vn);
        __nv_bfloat16 h, l;
        split1(vx, h, l); g_xhi[idx]  = h; g_xlo[idx]  = l;
        split1(vn, h, l); g_nxhi[idx] = h; g_nxlo[idx] = l;
    }
    __syncthreads();
#pragma unroll
    for (int i = ty; i < 32; i += 8)
        g_a[(size_t)(k0 + i) * COLS + c0 + tx] = tile[tx][i];
}
__global__ void prepsplit_w_kernel(const float* __restrict__ w, const float* __restrict__ wn) {
    __shared__ float tile[32][33];
    int c0 = blockIdx.x * 32, k0 = blockIdx.y * 32;
    int tx = threadIdx.x, ty = threadIdx.y;
#pragma unroll
    for (int i = ty; i < 32; i += 8) {
        size_t idx = (size_t)(c0 + i) * IN_F + k0 + tx;
        float vw = w[idx], vn = wn[idx];
        float vp = __fadd_rn(vw, vn);
        tile[i][tx] = vp;
        __nv_bfloat16 h, l;
        split1(vn, h, l); g_wnhi[idx] = h; g_wnlo[idx] = l;
        split1(vp, h, l); g_wphi[idx] = h; g_wplo[idx] = l;
    }
    __syncthreads();
#pragma unroll
    for (int i = ty; i < 32; i += 8)
        g_a[(size_t)(k0 + i) * COLS + BSZ + c0 + tx] = tile[tx][i];
}

// ---------------- TWO fused permutation + 2x2-mix rounds (bitwise-exact, NO FMA) ----
__global__ void round2_kernel(int dir, int r,
                              const int* __restrict__ perm0,
                              const int* __restrict__ perm1,
                              const float* __restrict__ matsx0,
                              const float* __restrict__ matsx1,
                              int do_mm) {
    const float* in  = dir ? g_b : g_a;
    float*       out = dir ? g_a : g_b;
    int g   = blockIdx.y;
    int col = blockIdx.x * 256 + threadIdx.x;
    int i0 = __ldg(&perm1[2 * g]);
    int i1 = __ldg(&perm1[2 * g + 1]);
    int g0 = i0 >> 1, p0 = i0 & 1;
    int g1 = i1 >> 1, p1 = i1 & 1;
    int ra0 = __ldg(&perm0[2 * g0]), rb0 = __ldg(&perm0[2 * g0 + 1]);
    int ra1 = __ldg(&perm0[2 * g1]), rb1 = __ldg(&perm0[2 * g1 + 1]);
    bool isx = (col < BSZ / 4);
    const float* m0base = isx ? matsx0 : (g_wmats + (size_t)r * GROUPS * 4);
    const float* m1base = isx ? matsx1 : (g_wmats + (size_t)(r + 1) * GROUPS * 4);
    float4 mA = __ldg((const float4*)(m0base + (size_t)g0 * 4));
    float4 mB = __ldg((const float4*)(m0base + (size_t)g1 * 4));
    float4 mC = __ldg((const float4*)(m1base + (size_t)g * 4));
    float c00 = p0 ? mA.z : mA.x, c01 = p0 ? mA.w : mA.y;
    float c10 = p1 ? mB.z : mB.x, c11 = p1 ? mB.w : mB.y;
    float4 a0 = ((const float4*)(in + (size_t)ra0 * COLS))[col];
    float4 b0 = ((const float4*)(in + (size_t)rb0 * COLS))[col];
    float4 a1 = ((const float4*)(in + (size_t)ra1 * COLS))[col];
    float4 b1 = ((const float4*)(in + (size_t)rb1 * COLS))[col];
    float4 v0, v1, o0, o1;
    v0.x = __fadd_rn(__fmul_rn(c00, a0.x), __fmul_rn(c01, b0.x));
    v0.y = __fadd_rn(__fmul_rn(c00, a0.y), __fmul_rn(c01, b0.y));
    v0.z = __fadd_rn(__fmul_rn(c00, a0.z), __fmul_rn(c01, b0.z));
    v0.w = __fadd_rn(__fmul_rn(c00, a0.w), __fmul_rn(c01, b0.w));
    v1.x = __fadd_rn(__fmul_rn(c10, a1.x), __fmul_rn(c11, b1.x));
    v1.y = __fadd_rn(__fmul_rn(c10, a1.y), __fmul_rn(c11, b1.y));
    v1.z = __fadd_rn(__fmul_rn(c10, a1.z), __fmul_rn(c11, b1.z));
    v1.w = __fadd_rn(__fmul_rn(c10, a1.w), __fmul_rn(c11, b1.w));
    o0.x = __fadd_rn(__fmul_rn(mC.x, v0.x), __fmul_rn(mC.y, v1.x));
    o0.y = __fadd_rn(__fmul_rn(mC.x, v0.y), __fmul_rn(mC.y, v1.y));
    o0.z = __fadd_rn(__fmul_rn(mC.x, v0.z), __fmul_rn(mC.y, v1.z));
    o0.w = __fadd_rn(__fmul_rn(mC.x, v0.w), __fmul_rn(mC.y, v1.w));
    o1.x = __fadd_rn(__fmul_rn(mC.z, v0.x), __fmul_rn(mC.w, v1.x));
    o1.y = __fadd_rn(__fmul_rn(mC.z, v0.y), __fmul_rn(mC.w, v1.y));
    o1.z = __fadd_rn(__fmul_rn(mC.z, v0.z), __fmul_rn(mC.w, v1.z));
    o1.w = __fadd_rn(__fmul_rn(mC.z, v0.w), __fmul_rn(mC.w, v1.w));
    ((float4*)(out + (size_t)(2 * g)     * COLS))[col] = o0;
    ((float4*)(out + (size_t)(2 * g + 1) * COLS))[col] = o1;

    if (do_mm) {
        float lo = fminf(fminf(fminf(o0.x, o0.y), fminf(o0.z, o0.w)),
                         fminf(fminf(o1.x, o1.y), fminf(o1.z, o1.w)));
        float hi = fmaxf(fmaxf(fmaxf(o0.x, o0.y), fmaxf(o0.z, o0.w)),
                         fmaxf(fmaxf(o1.x, o1.y), fmaxf(o1.z, o1.w)));
        __shared__ float red[256];
        red[threadIdx.x] = lo; __syncthreads();
        for (int s = 128; s > 0; s >>= 1) {
            if (threadIdx.x < s) red[threadIdx.x] = fminf(red[threadIdx.x], red[threadIdx.x + s]);
            __syncthreads();
        }
        if (threadIdx.x == 0) atomicMin(&g_mm[isx ? 0 : 2], enc_f(red[0]));
        __syncthreads();
        red[threadIdx.x] = hi; __syncthreads();
        for (int s = 128; s > 0; s >>= 1) {
            if (threadIdx.x < s) red[threadIdx.x] = fmaxf(red[threadIdx.x], red[threadIdx.x + s]);
            __syncthreads();
        }
        if (threadIdx.x == 0) atomicMax(&g_mm[isx ? 1 : 3], enc_f(red[0]));
    }
}

// ---------------- reset + qparams ----------------
__global__ void reset_kernel() {
    if (threadIdx.x == 0) {
        g_mm[0] = 0xFFFFFFFFu; g_mm[1] = 0u;
        g_mm[2] = 0xFFFFFFFFu; g_mm[3] = 0u;
    }
}
__global__ void qparams_kernel() {
    if (threadIdx.x == 0) {
        float lx = dec_f(g_mm[0]), hx = dec_f(g_mm[1]);
        float sx = __fdiv_rn(__fsub_rn(hx, lx), 255.0f);
        float zx = rintf(__fsub_rn(-128.0f, __fdiv_rn(lx, sx)));
        float lw = dec_f(g_mm[2]), hw = dec_f(g_mm[3]);
        float sw = __fdiv_rn(__fsub_rn(hw, lw), 255.0f);
        float zw = rintf(__fsub_rn(-128.0f, __fdiv_rn(lw, sw)));
        g_qp[0] = sx; g_qp[1] = zx; g_qp[2] = sw; g_qp[3] = zw;
    }
}

// ---------------- quantize -> integer (q - zp) bf16, K-major ----------------
__global__ void quantT_kernel() {
    __shared__ float tile[32][33];
    int c0 = blockIdx.x * 32, k0 = blockIdx.y * 32;
    int tx = threadIdx.x, ty = threadIdx.y;
    bool isx = (c0 < BSZ);
    float s = isx ? g_qp[0] : g_qp[2];
    float z = isx ? g_qp[1] : g_qp[3];
#pragma unroll
    for (int i = ty; i < 32; i += 8) {
        float t = g_a[(size_t)(k0 + i) * COLS + c0 + tx];
        float q = rintf(__fadd_rn(__fdiv_rn(t, s), z));
        q = fminf(fmaxf(q, -128.0f), 127.0f);
        tile[i][tx] = __fsub_rn(q, z);
    }
    __syncthreads();
    __nv_bfloat16* dst = isx ? g_qx : g_qw;
    int cb = isx ? c0 : (c0 - BSZ);
#pragma unroll
    for (int i = ty; i < 32; i += 8) {
        dst[(size_t)(cb + i) * IN_F + k0 + tx] = __float2bfloat16_rn(tile[tx][i]);
    }
}

// ---------------- shared GEMM body pieces ----------------
#define GEMM_PROLOG()                                                          \
    extern __shared__ __align__(1024) char smem[];                             \
    uint32_t sb = smem_u32(smem);                                              \
    const int tid = threadIdx.x, lane = tid & 31, warp = tid >> 5;             \
    const int bn = blockIdx.x, bm = blockIdx.y;                                \
    const int wm = (warp >> 2) * 64, wn = (warp & 3) * 32;                     \
    if (tid == 0) {                                                            \
        for (int i = 0; i < NSTG; i++) MBAR_INIT(sb + i * 8, 1);               \
    }                                                                          \
    __syncthreads();                                                           \
    float acc[4][4][4];                                                        \
    for (int a = 0; a < 4; a++)                                                \
        for (int b = 0; b < 4; b++)                                            \
            for (int c = 0; c < 4; c++) acc[a][b][c] = 0.0f;

#define GEMM_CHUNK(abase, bbase)                                               \
    for (int kq = 0; kq < 4; kq++) {                                           \
        uint32_t af[4][4], bf[4][2];                                           \
        for (int mt = 0; mt < 4; mt++) {                                       \
            int row = wm + mt * 16 + (lane & 15);                              \
            int chk = kq * 2 + (lane >> 4);                                    \
            uint32_t off = (uint32_t)(row * 128 + chk * 16);                   \
            uint32_t ad = (abase) + (off ^ ((off >> 3) & 0x70));               \
            asm volatile("ldmatrix.sync.aligned.m8n8.x4.shared.b16 {%0,%1,%2,%3},[%4];" \
                         : "=r"(af[mt][0]), "=r"(af[mt][1]), "=r"(af[mt][2]), "=r"(af[mt][3]) \
                         : "r"(ad));                                           \
        }                                                                      \
        for (int nt = 0; nt < 4; nt++) {                                       \
            int row = wn + nt * 8 + (lane & 7);                                \
            int chk = kq * 2 + ((lane >> 3) & 1);                              \
            uint32_t off = (uint32_t)(row * 128 + chk * 16);                   \
            uint32_t bd = (bbase) + (off ^ ((off >> 3) & 0x70));               \
            asm volatile("ldmatrix.sync.aligned.m8n8.x2.shared.b16 {%0,%1},[%2];" \
                         : "=r"(bf[nt][0]), "=r"(bf[nt][1]) : "r"(bd));        \
        }                                                                      \
        for (int mt = 0; mt < 4; mt++)                                         \
            for (int nt = 0; nt < 4; nt++) {                                   \
                asm volatile(                                                  \
                    "mma.sync.aligned.m16n8k16.row.col.f32.bf16.bf16.f32 "     \
                    "{%0,%1,%2,%3},{%4,%5,%6,%7},{%8,%9},{%0,%1,%2,%3};"       \
                    : "+f"(acc[mt][nt][0]), "+f"(acc[mt][nt][1]),              \
                      "+f"(acc[mt][nt][2]), "+f"(acc[mt][nt][3])               \
                    : "r"(af[mt][0]), "r"(af[mt][1]), "r"(af[mt][2]), "r"(af[mt][3]), \
                      "r"(bf[nt][0]), "r"(bf[nt][1]));                         \
            }                                                                  \
    }

#define GEMM_EPILOG(dst)                                                       \
    {                                                                          \
        const int grp = lane >> 2, tig = lane & 3;                             \
        for (int mt = 0; mt < 4; mt++)                                         \
            for (int nt = 0; nt < 4; nt++) {                                   \
                int gm = bm * 128 + wm + mt * 16 + grp;                        \
                int gn = bn * 128 + wn + nt * 8 + tig * 2;                     \
                float2 v0, v1;                                                 \
                v0.x = acc[mt][nt][0]; v0.y = acc[mt][nt][1];                  \
                v1.x = acc[mt][nt][2]; v1.y = acc[mt][nt][3];                  \
                *(float2*)&(dst)[(size_t)gm * OUT_F + gn]       = v0;          \
                *(float2*)&(dst)[(size_t)(gm + 8) * OUT_F + gn] = v1;          \
            }                                                                  \
    }

// ---------------- correction GEMM (segs 1..6), K-split z=4 ----------------
__global__ void __launch_bounds__(256)
gemm_corr_kernel(const __grid_constant__ TmapPack tp) {
    GEMM_PROLOG();
    const int bz = blockIdx.z;
    const int kbase = bz * (IN_F / NZ);
    float* part = g_part[bz];
    static const int aselc[NSEGC] = {1, 1, 2, 3, 3, 4};
    static const int bselc[NSEGC] = {1, 2, 1, 3, 4, 3};

    if (tid == 0) {
#pragma unroll
        for (int p = 0; p < NSTG; p++) {
            int kx = kbase + p * KCH;   // p < 3 -> seg index 0 (panel 1)
            uint32_t st = sb + 1024 + p * ST_BYTES;
            MBAR_EXPECT_TX(sb + p * 8, ST_BYTES);
            TMA_2D(st,           &tp.a[1], kx, bm * 128, sb + p * 8);
            TMA_2D(st + A_BYTES, &tp.b[1], kx, bn * 128, sb + p * 8);
        }
    }
    for (int c = 0; c < NCHC; c++) {
        int s = c % NSTG, ph = (c / NSTG) & 1;
        MBAR_WAIT(sb + s * 8, ph);
        uint32_t abase = sb + 1024 + s * ST_BYTES;
        uint32_t bbase = abase + A_BYTES;
        GEMM_CHUNK(abase, bbase);
        __syncthreads();
        if (tid == 0 && c + NSTG < NCHC) {
            int nc = c + NSTG;
            int seg = nc / CHPSU, kx = kbase + (nc % CHPSU) * KCH;
            uint32_t st = sb + 1024 + s * ST_BYTES;
            MBAR_EXPECT_TX(sb + s * 8, ST_BYTES);
            TMA_2D(st,           &tp.a[aselc[seg]], kx, bm * 128, sb + s * 8);
            TMA_2D(st + A_BYTES, &tp.b[bselc[seg]], kx, bn * 128, sb + s * 8);
        }
    }
    GEMM_EPILOG(part);
}

// ---------------- quant GEMM (seg 0 only), full K ----------------
__global__ void __launch_bounds__(256)
gemm_q_kernel(const __grid_constant__ TmapPack tp) {
    GEMM_PROLOG();
    if (tid == 0) {
#pragma unroll
        for (int p = 0; p < NSTG; p++) {
            uint32_t st = sb + 1024 + p * ST_BYTES;
            MBAR_EXPECT_TX(sb + p * 8, ST_BYTES);
            TMA_2D(st,           &tp.a[0], p * KCH, bm * 128, sb + p * 8);
            TMA_2D(st + A_BYTES, &tp.b[0], p * KCH, bn * 128, sb + p * 8);
        }
    }
    for (int c = 0; c < NCHQ; c++) {
        int s = c % NSTG, ph = (c / NSTG) & 1;
        MBAR_WAIT(sb + s * 8, ph);
        uint32_t abase = sb + 1024 + s * ST_BYTES;
        uint32_t bbase = abase + A_BYTES;
        GEMM_CHUNK(abase, bbase);
        __syncthreads();
        if (tid == 0 && c + NSTG < NCHQ) {
            int nc = c + NSTG;
            uint32_t st = sb + 1024 + s * ST_BYTES;
            MBAR_EXPECT_TX(sb + s * 8, ST_BYTES);
            TMA_2D(st,           &tp.a[0], nc * KCH, bm * 128, sb + s * 8);
            TMA_2D(st + A_BYTES, &tp.b[0], nc * KCH, bn * 128, sb + s * 8);
        }
    }
    const float ss = __fmul_rn(g_qp[0], g_qp[2]);
#pragma unroll
    for (int a = 0; a < 4; a++)
#pragma unroll
        for (int b = 0; b < 4; b++)
#pragma unroll
            for (int q = 0; q < 4; q++) acc[a][b][q] = __fmul_rn(acc[a][b][q], ss);
    GEMM_EPILOG(g_qpart);
}

// ---------------- reduce: out = bias + q - (p0 + p1 + p2 + p3) ----------------
__global__ void reduce_kernel(const float* __restrict__ bias, float* __restrict__ out) {
    size_t i = (size_t)blockIdx.x * blockDim.x + threadIdx.x;   // float4 index
    const size_t N4 = (size_t)BSZ * OUT_F / 4;
    if (i >= N4) return;
    float4 qv = ((const float4*)g_qpart)[i];
    float4 a = ((const float4*)g_part[0])[i];
    float4 b = ((const float4*)g_part[1])[i];
    float4 c = ((const float4*)g_part[2])[i];
    float4 d = ((const float4*)g_part[3])[i];
    int gn = (int)((i * 4) & (OUT_F - 1));
    float4 bj = *(const float4*)&bias[gn];
    float4 o;
    o.x = __fsub_rn(__fadd_rn(bj.x, qv.x), __fadd_rn(__fadd_rn(a.x, b.x), __fadd_rn(c.x, d.x)));
    o.y = __fsub_rn(__fadd_rn(bj.y, qv.y), __fadd_rn(__fadd_rn(a.y, b.y), __fadd_rn(c.y, d.y)));
    o.z = __fsub_rn(__fadd_rn(bj.z, qv.z), __fadd_rn(__fadd_rn(a.z, b.z), __fadd_rn(c.z, d.z)));
    o.w = __fsub_rn(__fadd_rn(bj.w, qv.w), __fadd_rn(__fadd_rn(a.w, b.w), __fadd_rn(c.w, d.w)));
    ((float4*)out)[i] = o;
}

// ---------------- host ----------------
typedef CUresult (*EncodeFn)(CUtensorMap*, CUtensorMapDataType, cuuint32_t, void*,
                             const cuuint64_t*, const cuuint64_t*, const cuuint32_t*,
                             const cuuint32_t*, CUtensorMapInterleave, CUtensorMapSwizzle,
                             CUtensorMapL2promotion, CUtensorMapFloatOOBfill);

static void encode_map(EncodeFn enc, CUtensorMap* m, void* ptr, int rows) {
    cuuint64_t dims[2]    = {(cuuint64_t)IN_F, (cuuint64_t)rows};
    cuuint64_t strides[1] = {(cuuint64_t)IN_F * 2};
    cuuint32_t box[2]     = {(cuuint32_t)KCH, 128};
    cuuint32_t estr[2]    = {1, 1};
    enc(m, CU_TENSOR_MAP_DATA_TYPE_BFLOAT16, 2, ptr, dims, strides, box, estr,
        CU_TENSOR_MAP_INTERLEAVE_NONE, CU_TENSOR_MAP_SWIZZLE_128B,
        CU_TENSOR_MAP_L2_PROMOTION_L2_128B, CU_TENSOR_MAP_FLOAT_OOB_FILL_NONE);
}

extern "C" void kernel_launch(void* const* d_in, const int* in_sizes, int n_in,
                              void* d_out, int out_size) {
    const float* x    = (const float*)d_in[0];
    const float* wgt  = (const float*)d_in[1];
    const float* bias = (const float*)d_in[2];
    const float* wn   = (const float*)d_in[3];
    const float* nx   = (const float*)d_in[4];
    const int*   perms= (const int*)  d_in[5];
    const float* mats = (const float*)d_in[6];
    float* out = (float*)d_out;

    // side stream + fork/join events (created once; capture-safe fork pattern)
    static cudaStream_t s2 = nullptr;
    if (!s2) cudaStreamCreateWithFlags(&s2, cudaStreamNonBlocking);
    cudaEvent_t evSplit, evCorr;
    cudaEventCreateWithFlags(&evSplit, cudaEventDisableTiming);
    cudaEventCreateWithFlags(&evCorr, cudaEventDisableTiming);

    make_wmats_kernel<<<(ROUNDS * GROUPS + 255) / 256, 256>>>(mats);
    reset_kernel<<<1, 32>>>();

    prepsplit_x_kernel<<<dim3(BSZ / 32, IN_F / 32), dim3(32, 8)>>>(x, nx);
    prepsplit_w_kernel<<<dim3(OUT_F / 32, IN_F / 32), dim3(32, 8)>>>(wgt, wn);

    // tensormaps
    void* fp = nullptr;
#if CUDART_VERSION >= 12050
    cudaDriverEntryPointQueryResult qr;
    cudaGetDriverEntryPointByVersion("cuTensorMapEncodeTiled", &fp, 12000,
                                     cudaEnableDefault, &qr);
#else
    cudaGetDriverEntryPoint("cuTensorMapEncodeTiled", &fp, cudaEnableDefault);
#endif
    EncodeFn enc = (EncodeFn)fp;

    void *p_qx, *p_xhi, *p_xlo, *p_nxhi, *p_nxlo, *p_qw, *p_wnhi, *p_wnlo, *p_wphi, *p_wplo;
    cudaGetSymbolAddress(&p_qx, g_qx);     cudaGetSymbolAddress(&p_xhi, g_xhi);
    cudaGetSymbolAddress(&p_xlo, g_xlo);   cudaGetSymbolAddress(&p_nxhi, g_nxhi);
    cudaGetSymbolAddress(&p_nxlo, g_nxlo); cudaGetSymbolAddress(&p_qw, g_qw);
    cudaGetSymbolAddress(&p_wnhi, g_wnhi); cudaGetSymbolAddress(&p_wnlo, g_wnlo);
    cudaGetSymbolAddress(&p_wphi, g_wphi); cudaGetSymbolAddress(&p_wplo, g_wplo);

    TmapPack tp;
    encode_map(enc, &tp.a[0], p_qx,   BSZ);
    encode_map(enc, &tp.a[1], p_xhi,  BSZ);
    encode_map(enc, &tp.a[2], p_xlo,  BSZ);
    encode_map(enc, &tp.a[3], p_nxhi, BSZ);
    encode_map(enc, &tp.a[4], p_nxlo, BSZ);
    encode_map(enc, &tp.b[0], p_qw,   OUT_F);
    encode_map(enc, &tp.b[1], p_wnhi, OUT_F);
    encode_map(enc, &tp.b[2], p_wnlo, OUT_F);
    encode_map(enc, &tp.b[3], p_wphi, OUT_F);
    encode_map(enc, &tp.b[4], p_wplo, OUT_F);

    cudaFuncSetAttribute(gemm_corr_kernel, cudaFuncAttributeMaxDynamicSharedMemorySize, DSMEM);
    cudaFuncSetAttribute(gemm_q_kernel, cudaFuncAttributeMaxDynamicSharedMemorySize, DSMEM);

    // fork: correction GEMM on s2 (depends only on splits)
    cudaEventRecord(evSplit, 0);
    cudaStreamWaitEvent(s2, evSplit, 0);
    gemm_corr_kernel<<<dim3(OUT_F / 128, BSZ / 128, NZ), 256, DSMEM, s2>>>(tp);
    cudaEventRecord(evCorr, s2);

    // main: transform rounds + quantization + quant GEMM
    for (int p = 0; p < ROUNDS / 2; p++) {
        int r = 2 * p;
        round2_kernel<<<dim3(COLS4 / 256, GROUPS), 256>>>(
            p & 1, r,
            perms + (size_t)r * IN_F, perms + (size_t)(r + 1) * IN_F,
            mats + (size_t)r * GROUPS * 4, mats + (size_t)(r + 1) * GROUPS * 4,
            (p == ROUNDS / 2 - 1) ? 1 : 0);
    }
    qparams_kernel<<<1, 32>>>();
    quantT_kernel<<<dim3(COLS / 32, IN_F / 32), dim3(32, 8)>>>();
    gemm_q_kernel<<<dim3(OUT_F / 128, BSZ / 128), 256, DSMEM>>>(tp);

    // join + reduce
    cudaStreamWaitEvent(0, evCorr, 0);
    reduce_kernel<<<(BSZ * OUT_F / 4 + 255) / 256, 256>>>(bias, out);
}